// round 5
// baseline (speedup 1.0000x reference)
#include <cuda_runtime.h>
#include <cuda_bf16.h>
#include <cstdint>

#define BB 2
#define TT 4096
#define CDIM 768
#define HH 12
#define DD 64
#define BT (BB*TT)   // 8192

// Scratch (allocation-free rule: __device__ globals)
// q/k/v hold tf32 bit patterns (written by projection GEMMs); ctx is f32.
__device__ float g_q[BT*CDIM];
__device__ float g_k[BT*CDIM];
__device__ float g_v[BT*CDIM];
__device__ float g_ctx[BT*CDIM];

// ---------------------------------------------------------------------------
// helpers
// ---------------------------------------------------------------------------
__device__ __forceinline__ unsigned f2tf(float f) {
    unsigned u;
    asm("cvt.rna.tf32.f32 %0, %1;" : "=r"(u) : "f"(f));
    return u;
}

__device__ __forceinline__ void mma_tf32(float c[4], const unsigned a[4],
                                         const unsigned b[2]) {
    asm volatile(
        "mma.sync.aligned.m16n8k8.row.col.f32.tf32.tf32.f32 "
        "{%0,%1,%2,%3}, {%4,%5,%6,%7}, {%8,%9}, {%0,%1,%2,%3};\n"
        : "+f"(c[0]), "+f"(c[1]), "+f"(c[2]), "+f"(c[3])
        : "r"(a[0]), "r"(a[1]), "r"(a[2]), "r"(a[3]),
          "r"(b[0]), "r"(b[1]));
}

__device__ __forceinline__ void cp_async16(uint32_t saddr, const void* gptr) {
    asm volatile("cp.async.cg.shared.global [%0], [%1], 16;"
                 :: "r"(saddr), "l"(gptr));
}
__device__ __forceinline__ void cp_async_commit() {
    asm volatile("cp.async.commit_group;");
}
__device__ __forceinline__ void cp_async_wait0() {
    asm volatile("cp.async.wait_group 0;");
}
__device__ __forceinline__ void cp_async_wait1() {
    asm volatile("cp.async.wait_group 1;");
}

// ---------------------------------------------------------------------------
// GEMM: Y[M,N] = X[M,K] * W[N,K]^T,  M=8192, N=K=768  (unchanged)
// ---------------------------------------------------------------------------
template <bool TF32_OUT>
__global__ __launch_bounds__(256) void gemm_mma_kernel(
    const float* __restrict__ X, const float* __restrict__ W,
    float* __restrict__ Y, float out_scale) {
    __shared__ unsigned As[128][36];
    __shared__ unsigned Bs[128][36];

    const int tid  = threadIdx.x;
    const int warp = tid >> 5;
    const int lane = tid & 31;
    const int gid  = lane >> 2;   // 0..7
    const int tig  = lane & 3;    // 0..3
    const int wm   = warp >> 2;   // 0..1
    const int wn   = warp & 3;    // 0..3

    const int m0 = blockIdx.y * 128;
    const int n0 = blockIdx.x * 128;

    const int lrow = tid >> 3;         // 0..31
    const int lcol = (tid & 7) * 4;    // 0..28

    float c[4][4][4];
#pragma unroll
    for (int mt = 0; mt < 4; mt++)
#pragma unroll
        for (int nt = 0; nt < 4; nt++)
#pragma unroll
            for (int i = 0; i < 4; i++) c[mt][nt][i] = 0.f;

    for (int k0 = 0; k0 < CDIM; k0 += 32) {
        float4 xa[4], wb[4];
#pragma unroll
        for (int i = 0; i < 4; i++) {
            xa[i] = *(const float4*)&X[(size_t)(m0 + lrow + i * 32) * CDIM + k0 + lcol];
            wb[i] = *(const float4*)&W[(size_t)(n0 + lrow + i * 32) * CDIM + k0 + lcol];
        }
        __syncthreads();
#pragma unroll
        for (int i = 0; i < 4; i++) {
            uint4 xu, wu;
            xu.x = f2tf(xa[i].x); xu.y = f2tf(xa[i].y);
            xu.z = f2tf(xa[i].z); xu.w = f2tf(xa[i].w);
            wu.x = f2tf(wb[i].x); wu.y = f2tf(wb[i].y);
            wu.z = f2tf(wb[i].z); wu.w = f2tf(wb[i].w);
            *(uint4*)&As[lrow + i * 32][lcol] = xu;
            *(uint4*)&Bs[lrow + i * 32][lcol] = wu;
        }
        __syncthreads();

#pragma unroll
        for (int ks = 0; ks < 4; ks++) {
            const int kb = ks * 8;
            unsigned a[4][4], b[4][2];
#pragma unroll
            for (int mt = 0; mt < 4; mt++) {
                const int r = wm * 64 + mt * 16 + gid;
                a[mt][0] = As[r][kb + tig];
                a[mt][1] = As[r + 8][kb + tig];
                a[mt][2] = As[r][kb + tig + 4];
                a[mt][3] = As[r + 8][kb + tig + 4];
            }
#pragma unroll
            for (int nt = 0; nt < 4; nt++) {
                const int rn = wn * 32 + nt * 8 + gid;
                b[nt][0] = Bs[rn][kb + tig];
                b[nt][1] = Bs[rn][kb + tig + 4];
            }
#pragma unroll
            for (int mt = 0; mt < 4; mt++)
#pragma unroll
                for (int nt = 0; nt < 4; nt++)
                    mma_tf32(c[mt][nt], a[mt], b[nt]);
        }
    }

#pragma unroll
    for (int mt = 0; mt < 4; mt++) {
        const int r = m0 + wm * 64 + mt * 16 + gid;
#pragma unroll
        for (int nt = 0; nt < 4; nt++) {
            const int cn = n0 + wn * 32 + nt * 8 + 2 * tig;
            if (TF32_OUT) {
                uint2 o01 = make_uint2(f2tf(c[mt][nt][0] * out_scale),
                                       f2tf(c[mt][nt][1] * out_scale));
                uint2 o23 = make_uint2(f2tf(c[mt][nt][2] * out_scale),
                                       f2tf(c[mt][nt][3] * out_scale));
                *(uint2*)&Y[(size_t)r * CDIM + cn]       = o01;
                *(uint2*)&Y[(size_t)(r + 8) * CDIM + cn] = o23;
            } else {
                *(float2*)&Y[(size_t)r * CDIM + cn] =
                    make_float2(c[mt][nt][0], c[mt][nt][1]);
                *(float2*)&Y[(size_t)(r + 8) * CDIM + cn] =
                    make_float2(c[mt][nt][2], c[mt][nt][3]);
            }
        }
    }
}

// ---------------------------------------------------------------------------
// Flash attention (causal), tf32 mma, online softmax.
// q-tile 128 rows, 256 thr = 8 warps (16 rows each); kv-tile 64 rows.
// K and V fully double-buffered; the {K,V} tile for iter jt+1 is issued as
// ONE cp.async group right after the loop-top sync of iter jt -> a full
// iteration of compute hides its latency. One __syncthreads per iteration.
// Second diagonal kv-tile is fully masked for warps 0-3 -> skipped.
// smem = (128*68 + 2*64*68 + 2*64*72)*4 = 104KB -> 2 blocks/SM, 16 warps.
// ---------------------------------------------------------------------------
#define KROW 68
#define VROW 72
#define ATTN_SMEM ((128 * KROW + 2 * 64 * KROW + 2 * 64 * VROW) * 4)

__global__ __launch_bounds__(256) void attn_mma_kernel(
    const float* __restrict__ q, const float* __restrict__ k,
    const float* __restrict__ v, float* __restrict__ ctx) {
    extern __shared__ unsigned sm[];
    unsigned* QPs = sm;                          // Q tile then P tile (128 x 68)
    unsigned* Ks0 = sm + 128 * KROW;
    unsigned* Ks1 = Ks0 + 64 * KROW;
    unsigned* Vs0 = Ks1 + 64 * KROW;
    unsigned* Vs1 = Vs0 + 64 * VROW;

    const int tid  = threadIdx.x;
    const int warp = tid >> 5;
    const int lane = tid & 31;
    const int gid  = lane >> 2;
    const int tig  = lane & 3;
    const int rw   = warp * 16 + gid;    // this thread's first local row (0..127)

    const int qti = gridDim.x - 1 - blockIdx.x;   // long blocks first
    const int h   = blockIdx.y;
    const int b   = blockIdx.z;
    const int q0  = qti * 128;
    const int kvTiles = 2 * qti + 2;

    const uint32_t qp_base = (uint32_t)__cvta_generic_to_shared(QPs);
    const uint32_t k_base[2] = {(uint32_t)__cvta_generic_to_shared(Ks0),
                                (uint32_t)__cvta_generic_to_shared(Ks1)};
    const uint32_t v_base[2] = {(uint32_t)__cvta_generic_to_shared(Vs0),
                                (uint32_t)__cvta_generic_to_shared(Vs1)};

    const int lrr = tid >> 4;            // 0..15 (row group for KV loads)
    const int lc4 = (tid & 15) * 4;      // 0..60
    const size_t hoff = (size_t)h * DD + lc4;

    // ---- prologue: Q (group 0) || KV[0] (group 1) ----
#pragma unroll
    for (int i = 0; i < 8; i++) {
        int rr = lrr + i * 16;
        cp_async16(qp_base + (rr * KROW + lc4) * 4,
                   &q[(size_t)(b * TT + q0 + rr) * CDIM + hoff]);
    }
    cp_async_commit();
#pragma unroll
    for (int i = 0; i < 4; i++) {
        int rr = lrr + i * 16;
        cp_async16(k_base[0] + (rr * KROW + lc4) * 4,
                   &k[(size_t)(b * TT + rr) * CDIM + hoff]);
        cp_async16(v_base[0] + (rr * VROW + lc4) * 4,
                   &v[(size_t)(b * TT + rr) * CDIM + hoff]);
    }
    cp_async_commit();
    cp_async_wait1();        // Q arrived; KV[0] may still fly
    __syncthreads();

    // Q fragments (held in registers for the whole q-tile)
    unsigned qa[8][4];
#pragma unroll
    for (int ks = 0; ks < 8; ks++) {
        qa[ks][0] = QPs[rw * KROW + ks * 8 + tig];
        qa[ks][1] = QPs[(rw + 8) * KROW + ks * 8 + tig];
        qa[ks][2] = QPs[rw * KROW + ks * 8 + tig + 4];
        qa[ks][3] = QPs[(rw + 8) * KROW + ks * 8 + tig + 4];
    }

    float o[8][4];
#pragma unroll
    for (int nt = 0; nt < 8; nt++)
#pragma unroll
        for (int i = 0; i < 4; i++) o[nt][i] = 0.f;
    float m0r = -1e30f, m1r = -1e30f, l0 = 0.f, l1 = 0.f;

    for (int jt = 0; jt < kvTiles; jt++) {
        const int buf = jt & 1;
        const unsigned* Kc = (buf ? Ks1 : Ks0);
        const unsigned* Vc = (buf ? Vs1 : Vs0);

        cp_async_wait0();     // KV[jt] fully arrived
        __syncthreads();      // publish KV[jt]; buffers for jt+1 now free

        // prefetch KV[jt+1] (one group) — hidden behind this iter's compute
        if (jt + 1 < kvTiles) {
            const int nb = buf ^ 1;
            const size_t gb = (size_t)(b * TT + (jt + 1) * 64) * CDIM + hoff;
#pragma unroll
            for (int i = 0; i < 4; i++) {
                int rr = lrr + i * 16;
                cp_async16(k_base[nb] + (rr * KROW + lc4) * 4,
                           &k[gb + (size_t)rr * CDIM]);
                cp_async16(v_base[nb] + (rr * VROW + lc4) * 4,
                           &v[gb + (size_t)rr * CDIM]);
            }
            cp_async_commit();
        }

        const int dq = jt - 2 * qti;   // >=0 on diagonal tiles
        // second diagonal tile: cols 64..127 vs rows 0..63 -> fully masked
        if (dq == 1 && warp < 4) continue;

        // S = Q K^T  (16 x 64 per warp)
        float s[8][4];
#pragma unroll
        for (int nt = 0; nt < 8; nt++)
#pragma unroll
            for (int i = 0; i < 4; i++) s[nt][i] = 0.f;

#pragma unroll
        for (int ks = 0; ks < 8; ks++) {
            const int kb = ks * 8;
#pragma unroll
            for (int nt = 0; nt < 8; nt++) {
                unsigned bb[2];
                const int rn = nt * 8 + gid;
                bb[0] = Kc[rn * KROW + kb + tig];
                bb[1] = Kc[rn * KROW + kb + tig + 4];
                mma_tf32(s[nt], qa[ks], bb);
            }
        }

        // causal mask on diagonal tiles
        if (dq >= 0) {
            const int cb = dq * 64;
#pragma unroll
            for (int nt = 0; nt < 8; nt++) {
                const int cg = cb + nt * 8 + 2 * tig;
                if (cg > rw)         s[nt][0] = -1e30f;
                if (cg + 1 > rw)     s[nt][1] = -1e30f;
                if (cg > rw + 8)     s[nt][2] = -1e30f;
                if (cg + 1 > rw + 8) s[nt][3] = -1e30f;
            }
        }

        // row maxima (two rows per thread)
        float mx0 = -1e30f, mx1 = -1e30f;
#pragma unroll
        for (int nt = 0; nt < 8; nt++) {
            mx0 = fmaxf(mx0, fmaxf(s[nt][0], s[nt][1]));
            mx1 = fmaxf(mx1, fmaxf(s[nt][2], s[nt][3]));
        }
        mx0 = fmaxf(mx0, __shfl_xor_sync(0xffffffffu, mx0, 1));
        mx0 = fmaxf(mx0, __shfl_xor_sync(0xffffffffu, mx0, 2));
        mx1 = fmaxf(mx1, __shfl_xor_sync(0xffffffffu, mx1, 1));
        mx1 = fmaxf(mx1, __shfl_xor_sync(0xffffffffu, mx1, 2));

        const float mn0 = fmaxf(m0r, mx0);
        const float mn1 = fmaxf(m1r, mx1);
        const float a0 = __expf(m0r - mn0);
        const float a1 = __expf(m1r - mn1);

        float ls0 = 0.f, ls1 = 0.f;
#pragma unroll
        for (int nt = 0; nt < 8; nt++) {
            s[nt][0] = __expf(s[nt][0] - mn0); ls0 += s[nt][0];
            s[nt][1] = __expf(s[nt][1] - mn0); ls0 += s[nt][1];
            s[nt][2] = __expf(s[nt][2] - mn1); ls1 += s[nt][2];
            s[nt][3] = __expf(s[nt][3] - mn1); ls1 += s[nt][3];
        }
        ls0 += __shfl_xor_sync(0xffffffffu, ls0, 1);
        ls0 += __shfl_xor_sync(0xffffffffu, ls0, 2);
        ls1 += __shfl_xor_sync(0xffffffffu, ls1, 1);
        ls1 += __shfl_xor_sync(0xffffffffu, ls1, 2);

        l0 = l0 * a0 + ls0; m0r = mn0;
        l1 = l1 * a1 + ls1; m1r = mn1;
#pragma unroll
        for (int nt = 0; nt < 8; nt++) {
            o[nt][0] *= a0; o[nt][1] *= a0;
            o[nt][2] *= a1; o[nt][3] *= a1;
        }

        // P -> smem as tf32 (warp-private 16-row band: __syncwarp only)
#pragma unroll
        for (int nt = 0; nt < 8; nt++) {
            const int cc = nt * 8 + 2 * tig;
            *(uint2*)&QPs[rw * KROW + cc] =
                make_uint2(f2tf(s[nt][0]), f2tf(s[nt][1]));
            *(uint2*)&QPs[(rw + 8) * KROW + cc] =
                make_uint2(f2tf(s[nt][2]), f2tf(s[nt][3]));
        }
        __syncwarp();

        // O += P V  (16 x 64 per warp) — V already resident
#pragma unroll
        for (int kc = 0; kc < 8; kc++) {
            const int kb = kc * 8;
            unsigned pa[4];
            pa[0] = QPs[rw * KROW + kb + tig];
            pa[1] = QPs[(rw + 8) * KROW + kb + tig];
            pa[2] = QPs[rw * KROW + kb + tig + 4];
            pa[3] = QPs[(rw + 8) * KROW + kb + tig + 4];
#pragma unroll
            for (int nt = 0; nt < 8; nt++) {
                unsigned bb[2];
                bb[0] = Vc[(kb + tig) * VROW + nt * 8 + gid];
                bb[1] = Vc[(kb + tig + 4) * VROW + nt * 8 + gid];
                mma_tf32(o[nt], pa, bb);
            }
        }
    }

    // epilogue (f32 out)
    const float inv0 = 1.f / l0;
    const float inv1 = 1.f / l1;
    const size_t r0 = (size_t)(b * TT + q0 + rw) * CDIM + h * DD;
    const size_t r1 = (size_t)(b * TT + q0 + rw + 8) * CDIM + h * DD;
#pragma unroll
    for (int nt = 0; nt < 8; nt++) {
        const int cc = nt * 8 + 2 * tig;
        *(float2*)&ctx[r0 + cc] = make_float2(o[nt][0] * inv0, o[nt][1] * inv0);
        *(float2*)&ctx[r1 + cc] = make_float2(o[nt][2] * inv1, o[nt][3] * inv1);
    }
}

// ---------------------------------------------------------------------------
extern "C" void kernel_launch(void* const* d_in, const int* in_sizes, int n_in,
                              void* d_out, int out_size) {
    const float* x  = (const float*)d_in[0];
    const float* wq = (const float*)d_in[1];
    const float* wk = (const float*)d_in[2];
    const float* wv = (const float*)d_in[3];
    const float* wo = (const float*)d_in[4];
    float* out = (float*)d_out;

    float* q;   cudaGetSymbolAddress((void**)&q,   g_q);
    float* kk;  cudaGetSymbolAddress((void**)&kk,  g_k);
    float* v;   cudaGetSymbolAddress((void**)&v,   g_v);
    float* ctx; cudaGetSymbolAddress((void**)&ctx, g_ctx);

    cudaFuncSetAttribute(attn_mma_kernel,
                         cudaFuncAttributeMaxDynamicSharedMemorySize, ATTN_SMEM);

    dim3 gg(CDIM / 128, BT / 128);
    // Q pre-scaled by 1/sqrt(D), written as tf32 bits
    gemm_mma_kernel<true><<<gg, 256>>>(x, wq, q, 0.125f);
    gemm_mma_kernel<true><<<gg, 256>>>(x, wk, kk, 1.0f);
    gemm_mma_kernel<true><<<gg, 256>>>(x, wv, v, 1.0f);

    dim3 ga(TT / 128, HH, BB);
    attn_mma_kernel<<<ga, 256, ATTN_SMEM>>>(q, kk, v, ctx);

    gemm_mma_kernel<false><<<gg, 256>>>(ctx, wo, out, 1.0f);
}

// round 6
// speedup vs baseline: 1.0701x; 1.0701x over previous
#include <cuda_runtime.h>
#include <cuda_bf16.h>
#include <cstdint>

#define BB 2
#define TT 4096
#define CDIM 768
#define HH 12
#define DD 64
#define BT (BB*TT)   // 8192

// Scratch (allocation-free rule: __device__ globals)
// q/k/v hold tf32 bit patterns (written by projection GEMMs); ctx is f32.
__device__ float g_q[BT*CDIM];
__device__ float g_k[BT*CDIM];
__device__ float g_v[BT*CDIM];
__device__ float g_ctx[BT*CDIM];

// ---------------------------------------------------------------------------
// helpers
// ---------------------------------------------------------------------------
__device__ __forceinline__ unsigned f2tf(float f) {
    unsigned u;
    asm("cvt.rna.tf32.f32 %0, %1;" : "=r"(u) : "f"(f));
    return u;
}

__device__ __forceinline__ void mma_tf32(float c[4], const unsigned a[4],
                                         const unsigned b[2]) {
    asm volatile(
        "mma.sync.aligned.m16n8k8.row.col.f32.tf32.tf32.f32 "
        "{%0,%1,%2,%3}, {%4,%5,%6,%7}, {%8,%9}, {%0,%1,%2,%3};\n"
        : "+f"(c[0]), "+f"(c[1]), "+f"(c[2]), "+f"(c[3])
        : "r"(a[0]), "r"(a[1]), "r"(a[2]), "r"(a[3]),
          "r"(b[0]), "r"(b[1]));
}

__device__ __forceinline__ void cp_async16(uint32_t saddr, const void* gptr) {
    asm volatile("cp.async.cg.shared.global [%0], [%1], 16;"
                 :: "r"(saddr), "l"(gptr));
}
__device__ __forceinline__ void cp_async_commit() {
    asm volatile("cp.async.commit_group;");
}
__device__ __forceinline__ void cp_async_wait0() {
    asm volatile("cp.async.wait_group 0;");
}
__device__ __forceinline__ void cp_async_wait1() {
    asm volatile("cp.async.wait_group 1;");
}

// ---------------------------------------------------------------------------
// GEMM: Y[M,N] = X[M,K] * W[N,K]^T,  M=8192, N=K=768  (unchanged)
// ---------------------------------------------------------------------------
template <bool TF32_OUT>
__global__ __launch_bounds__(256) void gemm_mma_kernel(
    const float* __restrict__ X, const float* __restrict__ W,
    float* __restrict__ Y, float out_scale) {
    __shared__ unsigned As[128][36];
    __shared__ unsigned Bs[128][36];

    const int tid  = threadIdx.x;
    const int warp = tid >> 5;
    const int lane = tid & 31;
    const int gid  = lane >> 2;   // 0..7
    const int tig  = lane & 3;    // 0..3
    const int wm   = warp >> 2;   // 0..1
    const int wn   = warp & 3;    // 0..3

    const int m0 = blockIdx.y * 128;
    const int n0 = blockIdx.x * 128;

    const int lrow = tid >> 3;         // 0..31
    const int lcol = (tid & 7) * 4;    // 0..28

    float c[4][4][4];
#pragma unroll
    for (int mt = 0; mt < 4; mt++)
#pragma unroll
        for (int nt = 0; nt < 4; nt++)
#pragma unroll
            for (int i = 0; i < 4; i++) c[mt][nt][i] = 0.f;

    for (int k0 = 0; k0 < CDIM; k0 += 32) {
        float4 xa[4], wb[4];
#pragma unroll
        for (int i = 0; i < 4; i++) {
            xa[i] = *(const float4*)&X[(size_t)(m0 + lrow + i * 32) * CDIM + k0 + lcol];
            wb[i] = *(const float4*)&W[(size_t)(n0 + lrow + i * 32) * CDIM + k0 + lcol];
        }
        __syncthreads();
#pragma unroll
        for (int i = 0; i < 4; i++) {
            uint4 xu, wu;
            xu.x = f2tf(xa[i].x); xu.y = f2tf(xa[i].y);
            xu.z = f2tf(xa[i].z); xu.w = f2tf(xa[i].w);
            wu.x = f2tf(wb[i].x); wu.y = f2tf(wb[i].y);
            wu.z = f2tf(wb[i].z); wu.w = f2tf(wb[i].w);
            *(uint4*)&As[lrow + i * 32][lcol] = xu;
            *(uint4*)&Bs[lrow + i * 32][lcol] = wu;
        }
        __syncthreads();

#pragma unroll
        for (int ks = 0; ks < 4; ks++) {
            const int kb = ks * 8;
            unsigned a[4][4], b[4][2];
#pragma unroll
            for (int mt = 0; mt < 4; mt++) {
                const int r = wm * 64 + mt * 16 + gid;
                a[mt][0] = As[r][kb + tig];
                a[mt][1] = As[r + 8][kb + tig];
                a[mt][2] = As[r][kb + tig + 4];
                a[mt][3] = As[r + 8][kb + tig + 4];
            }
#pragma unroll
            for (int nt = 0; nt < 4; nt++) {
                const int rn = wn * 32 + nt * 8 + gid;
                b[nt][0] = Bs[rn][kb + tig];
                b[nt][1] = Bs[rn][kb + tig + 4];
            }
#pragma unroll
            for (int mt = 0; mt < 4; mt++)
#pragma unroll
                for (int nt = 0; nt < 4; nt++)
                    mma_tf32(c[mt][nt], a[mt], b[nt]);
        }
    }

#pragma unroll
    for (int mt = 0; mt < 4; mt++) {
        const int r = m0 + wm * 64 + mt * 16 + gid;
#pragma unroll
        for (int nt = 0; nt < 4; nt++) {
            const int cn = n0 + wn * 32 + nt * 8 + 2 * tig;
            if (TF32_OUT) {
                uint2 o01 = make_uint2(f2tf(c[mt][nt][0] * out_scale),
                                       f2tf(c[mt][nt][1] * out_scale));
                uint2 o23 = make_uint2(f2tf(c[mt][nt][2] * out_scale),
                                       f2tf(c[mt][nt][3] * out_scale));
                *(uint2*)&Y[(size_t)r * CDIM + cn]       = o01;
                *(uint2*)&Y[(size_t)(r + 8) * CDIM + cn] = o23;
            } else {
                *(float2*)&Y[(size_t)r * CDIM + cn] =
                    make_float2(c[mt][nt][0], c[mt][nt][1]);
                *(float2*)&Y[(size_t)(r + 8) * CDIM + cn] =
                    make_float2(c[mt][nt][2], c[mt][nt][3]);
            }
        }
    }
}

// ---------------------------------------------------------------------------
// Flash attention (causal), tf32 mma, online softmax.
// EXACT loop structure of the 488us kernel (serial K/V load, wait0,
// 2 syncthreads/iter). Single change: P buffer merged into Q smem region
// (Q fragments live in registers after prologue), 69KB -> 52KB smem
// -> 4 blocks/SM, 16 warps. __launch_bounds__(128,4) pins regs <= 128.
// ---------------------------------------------------------------------------
#define KROW 68
#define VROW 72
#define ATTN_SMEM ((2 * 64 * KROW + 64 * VROW) * 4)

__global__ __launch_bounds__(128, 4) void attn_mma_kernel(
    const float* __restrict__ q, const float* __restrict__ k,
    const float* __restrict__ v, float* __restrict__ ctx) {
    extern __shared__ unsigned sm[];
    unsigned* QPs = sm;                  // Q tile, then P tile
    unsigned* Ks  = sm + 64 * KROW;
    unsigned* Vs  = sm + 2 * 64 * KROW;

    const int tid  = threadIdx.x;
    const int warp = tid >> 5;
    const int lane = tid & 31;
    const int gid  = lane >> 2;
    const int tig  = lane & 3;
    const int rw   = warp * 16 + gid;    // this thread's first local row

    const int qt = gridDim.x - 1 - blockIdx.x;   // long blocks first
    const int h  = blockIdx.y;
    const int b  = blockIdx.z;
    const int q0 = qt * 64;

    const uint32_t qp_base = (uint32_t)__cvta_generic_to_shared(QPs);
    const uint32_t ks_base = (uint32_t)__cvta_generic_to_shared(Ks);
    const uint32_t vs_base = (uint32_t)__cvta_generic_to_shared(Vs);

    // Q tile: raw copy (already scaled tf32 bits)
    for (int e = tid; e < 1024; e += 128) {
        int rr = e >> 4, c4 = (e & 15) * 4;
        cp_async16(qp_base + (rr * KROW + c4) * 4,
                   &q[(size_t)(b * TT + q0 + rr) * CDIM + h * DD + c4]);
    }
    cp_async_commit();
    cp_async_wait0();
    __syncthreads();

    // Q fragments (held in registers for the whole q-tile)
    unsigned qa[8][4];
#pragma unroll
    for (int ks = 0; ks < 8; ks++) {
        qa[ks][0] = QPs[rw * KROW + ks * 8 + tig];
        qa[ks][1] = QPs[(rw + 8) * KROW + ks * 8 + tig];
        qa[ks][2] = QPs[rw * KROW + ks * 8 + tig + 4];
        qa[ks][3] = QPs[(rw + 8) * KROW + ks * 8 + tig + 4];
    }

    float o[8][4];
#pragma unroll
    for (int nt = 0; nt < 8; nt++)
#pragma unroll
        for (int i = 0; i < 4; i++) o[nt][i] = 0.f;
    float m0r = -1e30f, m1r = -1e30f, l0 = 0.f, l1 = 0.f;

    for (int jt = 0; jt <= qt; jt++) {
        __syncthreads();   // prior compute done before smem overwrite
        for (int e = tid; e < 1024; e += 128) {
            int rr = e >> 4, c4 = (e & 15) * 4;
            size_t gbase = (size_t)(b * TT + jt * 64 + rr) * CDIM + h * DD + c4;
            cp_async16(ks_base + (rr * KROW + c4) * 4, &k[gbase]);
            cp_async16(vs_base + (rr * VROW + c4) * 4, &v[gbase]);
        }
        cp_async_commit();
        cp_async_wait0();
        __syncthreads();

        // S = Q K^T  (16 x 64 per warp)
        float s[8][4];
#pragma unroll
        for (int nt = 0; nt < 8; nt++)
#pragma unroll
            for (int i = 0; i < 4; i++) s[nt][i] = 0.f;

#pragma unroll
        for (int ks = 0; ks < 8; ks++) {
            const int kb = ks * 8;
#pragma unroll
            for (int nt = 0; nt < 8; nt++) {
                unsigned bb[2];
                const int rn = nt * 8 + gid;
                bb[0] = Ks[rn * KROW + kb + tig];
                bb[1] = Ks[rn * KROW + kb + tig + 4];
                mma_tf32(s[nt], qa[ks], bb);
            }
        }

        // causal mask (diagonal tile only)
        if (jt == qt) {
#pragma unroll
            for (int nt = 0; nt < 8; nt++) {
                const int cg = nt * 8 + 2 * tig;
                if (cg > rw)         s[nt][0] = -1e30f;
                if (cg + 1 > rw)     s[nt][1] = -1e30f;
                if (cg > rw + 8)     s[nt][2] = -1e30f;
                if (cg + 1 > rw + 8) s[nt][3] = -1e30f;
            }
        }

        // row maxima (two rows per thread)
        float mx0 = -1e30f, mx1 = -1e30f;
#pragma unroll
        for (int nt = 0; nt < 8; nt++) {
            mx0 = fmaxf(mx0, fmaxf(s[nt][0], s[nt][1]));
            mx1 = fmaxf(mx1, fmaxf(s[nt][2], s[nt][3]));
        }
        mx0 = fmaxf(mx0, __shfl_xor_sync(0xffffffffu, mx0, 1));
        mx0 = fmaxf(mx0, __shfl_xor_sync(0xffffffffu, mx0, 2));
        mx1 = fmaxf(mx1, __shfl_xor_sync(0xffffffffu, mx1, 1));
        mx1 = fmaxf(mx1, __shfl_xor_sync(0xffffffffu, mx1, 2));

        const float mn0 = fmaxf(m0r, mx0);
        const float mn1 = fmaxf(m1r, mx1);
        const float a0 = __expf(m0r - mn0);
        const float a1 = __expf(m1r - mn1);

        float ls0 = 0.f, ls1 = 0.f;
#pragma unroll
        for (int nt = 0; nt < 8; nt++) {
            s[nt][0] = __expf(s[nt][0] - mn0); ls0 += s[nt][0];
            s[nt][1] = __expf(s[nt][1] - mn0); ls0 += s[nt][1];
            s[nt][2] = __expf(s[nt][2] - mn1); ls1 += s[nt][2];
            s[nt][3] = __expf(s[nt][3] - mn1); ls1 += s[nt][3];
        }
        ls0 += __shfl_xor_sync(0xffffffffu, ls0, 1);
        ls0 += __shfl_xor_sync(0xffffffffu, ls0, 2);
        ls1 += __shfl_xor_sync(0xffffffffu, ls1, 1);
        ls1 += __shfl_xor_sync(0xffffffffu, ls1, 2);

        l0 = l0 * a0 + ls0; m0r = mn0;
        l1 = l1 * a1 + ls1; m1r = mn1;
#pragma unroll
        for (int nt = 0; nt < 8; nt++) {
            o[nt][0] *= a0; o[nt][1] *= a0;
            o[nt][2] *= a1; o[nt][3] *= a1;
        }

        // P -> smem as tf32 (warp-private 16-row band: __syncwarp only)
#pragma unroll
        for (int nt = 0; nt < 8; nt++) {
            const int cc = nt * 8 + 2 * tig;
            *(uint2*)&QPs[rw * KROW + cc] =
                make_uint2(f2tf(s[nt][0]), f2tf(s[nt][1]));
            *(uint2*)&QPs[(rw + 8) * KROW + cc] =
                make_uint2(f2tf(s[nt][2]), f2tf(s[nt][3]));
        }
        __syncwarp();

        // O += P V  (16 x 64 per warp)
#pragma unroll
        for (int kc = 0; kc < 8; kc++) {
            const int kb = kc * 8;
            unsigned pa[4];
            pa[0] = QPs[rw * KROW + kb + tig];
            pa[1] = QPs[(rw + 8) * KROW + kb + tig];
            pa[2] = QPs[rw * KROW + kb + tig + 4];
            pa[3] = QPs[(rw + 8) * KROW + kb + tig + 4];
#pragma unroll
            for (int nt = 0; nt < 8; nt++) {
                unsigned bb[2];
                bb[0] = Vs[(kb + tig) * VROW + nt * 8 + gid];
                bb[1] = Vs[(kb + tig + 4) * VROW + nt * 8 + gid];
                mma_tf32(o[nt], pa, bb);
            }
        }
    }

    // epilogue (f32 out)
    const float inv0 = 1.f / l0;
    const float inv1 = 1.f / l1;
    const size_t r0 = (size_t)(b * TT + q0 + rw) * CDIM + h * DD;
    const size_t r1 = (size_t)(b * TT + q0 + rw + 8) * CDIM + h * DD;
#pragma unroll
    for (int nt = 0; nt < 8; nt++) {
        const int cc = nt * 8 + 2 * tig;
        *(float2*)&ctx[r0 + cc] = make_float2(o[nt][0] * inv0, o[nt][1] * inv0);
        *(float2*)&ctx[r1 + cc] = make_float2(o[nt][2] * inv1, o[nt][3] * inv1);
    }
}

// ---------------------------------------------------------------------------
extern "C" void kernel_launch(void* const* d_in, const int* in_sizes, int n_in,
                              void* d_out, int out_size) {
    const float* x  = (const float*)d_in[0];
    const float* wq = (const float*)d_in[1];
    const float* wk = (const float*)d_in[2];
    const float* wv = (const float*)d_in[3];
    const float* wo = (const float*)d_in[4];
    float* out = (float*)d_out;

    float* q;   cudaGetSymbolAddress((void**)&q,   g_q);
    float* kk;  cudaGetSymbolAddress((void**)&kk,  g_k);
    float* v;   cudaGetSymbolAddress((void**)&v,   g_v);
    float* ctx; cudaGetSymbolAddress((void**)&ctx, g_ctx);

    cudaFuncSetAttribute(attn_mma_kernel,
                         cudaFuncAttributeMaxDynamicSharedMemorySize, ATTN_SMEM);

    dim3 gg(CDIM / 128, BT / 128);
    // Q pre-scaled by 1/sqrt(D), written as tf32 bits
    gemm_mma_kernel<true><<<gg, 256>>>(x, wq, q, 0.125f);
    gemm_mma_kernel<true><<<gg, 256>>>(x, wk, kk, 1.0f);
    gemm_mma_kernel<true><<<gg, 256>>>(x, wv, v, 1.0f);

    dim3 ga(TT / 64, HH, BB);
    attn_mma_kernel<<<ga, 128, ATTN_SMEM>>>(q, kk, v, ctx);

    gemm_mma_kernel<false><<<gg, 256>>>(ctx, wo, out, 1.0f);
}

// round 7
// speedup vs baseline: 1.4973x; 1.3992x over previous
#include <cuda_runtime.h>
#include <cuda_bf16.h>
#include <cstdint>

#define BB 2
#define TT 4096
#define CDIM 768
#define HH 12
#define DD 64
#define BT (BB*TT)   // 8192

// Scratch (allocation-free rule: __device__ globals)
// q/k/v hold tf32 bit patterns (written by projection GEMMs); ctx is f32.
__device__ float g_q[BT*CDIM];
__device__ float g_k[BT*CDIM];
__device__ float g_v[BT*CDIM];
__device__ float g_ctx[BT*CDIM];

// ---------------------------------------------------------------------------
// helpers
// ---------------------------------------------------------------------------
__device__ __forceinline__ unsigned f2tf(float f) {
    unsigned u;
    asm("cvt.rna.tf32.f32 %0, %1;" : "=r"(u) : "f"(f));
    return u;
}

__device__ __forceinline__ void mma_tf32(float c[4], const unsigned a[4],
                                         const unsigned b[2]) {
    asm volatile(
        "mma.sync.aligned.m16n8k8.row.col.f32.tf32.tf32.f32 "
        "{%0,%1,%2,%3}, {%4,%5,%6,%7}, {%8,%9}, {%0,%1,%2,%3};\n"
        : "+f"(c[0]), "+f"(c[1]), "+f"(c[2]), "+f"(c[3])
        : "r"(a[0]), "r"(a[1]), "r"(a[2]), "r"(a[3]),
          "r"(b[0]), "r"(b[1]));
}

__device__ __forceinline__ void cp_async16(uint32_t saddr, const void* gptr) {
    asm volatile("cp.async.cg.shared.global [%0], [%1], 16;"
                 :: "r"(saddr), "l"(gptr));
}
__device__ __forceinline__ void cp_async_commit() {
    asm volatile("cp.async.commit_group;");
}
__device__ __forceinline__ void cp_async_wait0() {
    asm volatile("cp.async.wait_group 0;");
}

// ---------------------------------------------------------------------------
// GEMM: Y[M,N] = X[M,K] * W[N,K]^T,  M=8192, N=K=768
// Block 128x128, BK=32, 256 thr = 8 warps (2M x 4N), warp tile 64x32.
// NEW: cp.async double-buffered pipeline. Raw f32 staged in smem (2 stages,
// 72KB); prefetch of k0+32 issued right after loop-top sync -> one full
// iteration of mma compute hides the load latency. tf32 cvt at fragment load
// (numerically identical to producer-side cvt).
// ---------------------------------------------------------------------------
template <bool TF32_OUT>
__global__ __launch_bounds__(256) void gemm_mma_kernel(
    const float* __restrict__ X, const float* __restrict__ W,
    float* __restrict__ Y, float out_scale) {
    __shared__ float As[2][128][36];
    __shared__ float Bs[2][128][36];

    const int tid  = threadIdx.x;
    const int warp = tid >> 5;
    const int lane = tid & 31;
    const int gid  = lane >> 2;   // 0..7
    const int tig  = lane & 3;    // 0..3
    const int wm   = warp >> 2;   // 0..1
    const int wn   = warp & 3;    // 0..3

    const int m0 = blockIdx.y * 128;
    const int n0 = blockIdx.x * 128;

    const int lrow = tid >> 3;         // 0..31
    const int lcol = (tid & 7) * 4;    // 0..28

    const uint32_t a_sm[2] = {(uint32_t)__cvta_generic_to_shared(&As[0][0][0]),
                              (uint32_t)__cvta_generic_to_shared(&As[1][0][0])};
    const uint32_t b_sm[2] = {(uint32_t)__cvta_generic_to_shared(&Bs[0][0][0]),
                              (uint32_t)__cvta_generic_to_shared(&Bs[1][0][0])};

    float c[4][4][4];
#pragma unroll
    for (int mt = 0; mt < 4; mt++)
#pragma unroll
        for (int nt = 0; nt < 4; nt++)
#pragma unroll
            for (int i = 0; i < 4; i++) c[mt][nt][i] = 0.f;

    // prologue: stage 0 <- k0 = 0
#pragma unroll
    for (int i = 0; i < 4; i++) {
        cp_async16(a_sm[0] + (((lrow + i * 32) * 36 + lcol) * 4),
                   &X[(size_t)(m0 + lrow + i * 32) * CDIM + lcol]);
        cp_async16(b_sm[0] + (((lrow + i * 32) * 36 + lcol) * 4),
                   &W[(size_t)(n0 + lrow + i * 32) * CDIM + lcol]);
    }
    cp_async_commit();

    for (int k0 = 0; k0 < CDIM; k0 += 32) {
        const int s = (k0 >> 5) & 1;
        cp_async_wait0();
        __syncthreads();            // stage s visible; stage s^1 free

        if (k0 + 32 < CDIM) {
            const int ns = s ^ 1;
#pragma unroll
            for (int i = 0; i < 4; i++) {
                cp_async16(a_sm[ns] + (((lrow + i * 32) * 36 + lcol) * 4),
                           &X[(size_t)(m0 + lrow + i * 32) * CDIM + k0 + 32 + lcol]);
                cp_async16(b_sm[ns] + (((lrow + i * 32) * 36 + lcol) * 4),
                           &W[(size_t)(n0 + lrow + i * 32) * CDIM + k0 + 32 + lcol]);
            }
            cp_async_commit();
        }

#pragma unroll
        for (int ks = 0; ks < 4; ks++) {
            const int kb = ks * 8;
            unsigned a[4][4], b[4][2];
#pragma unroll
            for (int mt = 0; mt < 4; mt++) {
                const int r = wm * 64 + mt * 16 + gid;
                a[mt][0] = f2tf(As[s][r][kb + tig]);
                a[mt][1] = f2tf(As[s][r + 8][kb + tig]);
                a[mt][2] = f2tf(As[s][r][kb + tig + 4]);
                a[mt][3] = f2tf(As[s][r + 8][kb + tig + 4]);
            }
#pragma unroll
            for (int nt = 0; nt < 4; nt++) {
                const int rn = wn * 32 + nt * 8 + gid;
                b[nt][0] = f2tf(Bs[s][rn][kb + tig]);
                b[nt][1] = f2tf(Bs[s][rn][kb + tig + 4]);
            }
#pragma unroll
            for (int mt = 0; mt < 4; mt++)
#pragma unroll
                for (int nt = 0; nt < 4; nt++)
                    mma_tf32(c[mt][nt], a[mt], b[nt]);
        }
    }

#pragma unroll
    for (int mt = 0; mt < 4; mt++) {
        const int r = m0 + wm * 64 + mt * 16 + gid;
#pragma unroll
        for (int nt = 0; nt < 4; nt++) {
            const int cn = n0 + wn * 32 + nt * 8 + 2 * tig;
            if (TF32_OUT) {
                uint2 o01 = make_uint2(f2tf(c[mt][nt][0] * out_scale),
                                       f2tf(c[mt][nt][1] * out_scale));
                uint2 o23 = make_uint2(f2tf(c[mt][nt][2] * out_scale),
                                       f2tf(c[mt][nt][3] * out_scale));
                *(uint2*)&Y[(size_t)r * CDIM + cn]       = o01;
                *(uint2*)&Y[(size_t)(r + 8) * CDIM + cn] = o23;
            } else {
                *(float2*)&Y[(size_t)r * CDIM + cn] =
                    make_float2(c[mt][nt][0], c[mt][nt][1]);
                *(float2*)&Y[(size_t)(r + 8) * CDIM + cn] =
                    make_float2(c[mt][nt][2], c[mt][nt][3]);
            }
        }
    }
}

// ---------------------------------------------------------------------------
// Flash attention (causal), tf32 mma, online softmax — EXACT 488us config.
// Separate P buffer, 69KB smem, 3 blocks/SM, serial K/V cp.async per tile,
// qt reversed. DO NOT TOUCH (rounds 4-6 all regressed deviations).
// ---------------------------------------------------------------------------
#define KROW 68
#define VROW 72
#define ATTN_SMEM ((3 * 64 * KROW + 64 * VROW) * 4)

__global__ __launch_bounds__(128) void attn_mma_kernel(
    const float* __restrict__ q, const float* __restrict__ k,
    const float* __restrict__ v, float* __restrict__ ctx) {
    extern __shared__ unsigned sm[];
    unsigned* Qs = sm;
    unsigned* Ks = sm + 64 * KROW;
    unsigned* Ps = sm + 2 * 64 * KROW;
    unsigned* Vs = sm + 3 * 64 * KROW;

    const int tid  = threadIdx.x;
    const int warp = tid >> 5;
    const int lane = tid & 31;
    const int gid  = lane >> 2;
    const int tig  = lane & 3;
    const int rw   = warp * 16 + gid;    // this thread's first local row

    const int qt = gridDim.x - 1 - blockIdx.x;   // long blocks first
    const int h  = blockIdx.y;
    const int b  = blockIdx.z;
    const int q0 = qt * 64;

    const uint32_t qs_base = (uint32_t)__cvta_generic_to_shared(Qs);
    const uint32_t ks_base = (uint32_t)__cvta_generic_to_shared(Ks);
    const uint32_t vs_base = (uint32_t)__cvta_generic_to_shared(Vs);

    // Q tile: raw copy (already scaled tf32 bits)
    for (int e = tid; e < 1024; e += 128) {
        int rr = e >> 4, c4 = (e & 15) * 4;
        cp_async16(qs_base + (rr * KROW + c4) * 4,
                   &q[(size_t)(b * TT + q0 + rr) * CDIM + h * DD + c4]);
    }
    cp_async_commit();
    cp_async_wait0();
    __syncthreads();

    // Q fragments (held for the whole q-tile)
    unsigned qa[8][4];
#pragma unroll
    for (int ks = 0; ks < 8; ks++) {
        qa[ks][0] = Qs[rw * KROW + ks * 8 + tig];
        qa[ks][1] = Qs[(rw + 8) * KROW + ks * 8 + tig];
        qa[ks][2] = Qs[rw * KROW + ks * 8 + tig + 4];
        qa[ks][3] = Qs[(rw + 8) * KROW + ks * 8 + tig + 4];
    }

    float o[8][4];
#pragma unroll
    for (int nt = 0; nt < 8; nt++)
#pragma unroll
        for (int i = 0; i < 4; i++) o[nt][i] = 0.f;
    float m0r = -1e30f, m1r = -1e30f, l0 = 0.f, l1 = 0.f;

    for (int jt = 0; jt <= qt; jt++) {
        __syncthreads();   // prior compute done before smem overwrite
        for (int e = tid; e < 1024; e += 128) {
            int rr = e >> 4, c4 = (e & 15) * 4;
            size_t gbase = (size_t)(b * TT + jt * 64 + rr) * CDIM + h * DD + c4;
            cp_async16(ks_base + (rr * KROW + c4) * 4, &k[gbase]);
            cp_async16(vs_base + (rr * VROW + c4) * 4, &v[gbase]);
        }
        cp_async_commit();
        cp_async_wait0();
        __syncthreads();

        // S = Q K^T  (16 x 64 per warp)
        float s[8][4];
#pragma unroll
        for (int nt = 0; nt < 8; nt++)
#pragma unroll
            for (int i = 0; i < 4; i++) s[nt][i] = 0.f;

#pragma unroll
        for (int ks = 0; ks < 8; ks++) {
            const int kb = ks * 8;
#pragma unroll
            for (int nt = 0; nt < 8; nt++) {
                unsigned bb[2];
                const int rn = nt * 8 + gid;
                bb[0] = Ks[rn * KROW + kb + tig];
                bb[1] = Ks[rn * KROW + kb + tig + 4];
                mma_tf32(s[nt], qa[ks], bb);
            }
        }

        // causal mask (diagonal tile only)
        if (jt == qt) {
#pragma unroll
            for (int nt = 0; nt < 8; nt++) {
                const int cg = nt * 8 + 2 * tig;
                if (cg > rw)         s[nt][0] = -1e30f;
                if (cg + 1 > rw)     s[nt][1] = -1e30f;
                if (cg > rw + 8)     s[nt][2] = -1e30f;
                if (cg + 1 > rw + 8) s[nt][3] = -1e30f;
            }
        }

        // row maxima (two rows per thread)
        float mx0 = -1e30f, mx1 = -1e30f;
#pragma unroll
        for (int nt = 0; nt < 8; nt++) {
            mx0 = fmaxf(mx0, fmaxf(s[nt][0], s[nt][1]));
            mx1 = fmaxf(mx1, fmaxf(s[nt][2], s[nt][3]));
        }
        mx0 = fmaxf(mx0, __shfl_xor_sync(0xffffffffu, mx0, 1));
        mx0 = fmaxf(mx0, __shfl_xor_sync(0xffffffffu, mx0, 2));
        mx1 = fmaxf(mx1, __shfl_xor_sync(0xffffffffu, mx1, 1));
        mx1 = fmaxf(mx1, __shfl_xor_sync(0xffffffffu, mx1, 2));

        const float mn0 = fmaxf(m0r, mx0);
        const float mn1 = fmaxf(m1r, mx1);
        const float a0 = __expf(m0r - mn0);
        const float a1 = __expf(m1r - mn1);

        float ls0 = 0.f, ls1 = 0.f;
#pragma unroll
        for (int nt = 0; nt < 8; nt++) {
            s[nt][0] = __expf(s[nt][0] - mn0); ls0 += s[nt][0];
            s[nt][1] = __expf(s[nt][1] - mn0); ls0 += s[nt][1];
            s[nt][2] = __expf(s[nt][2] - mn1); ls1 += s[nt][2];
            s[nt][3] = __expf(s[nt][3] - mn1); ls1 += s[nt][3];
        }
        ls0 += __shfl_xor_sync(0xffffffffu, ls0, 1);
        ls0 += __shfl_xor_sync(0xffffffffu, ls0, 2);
        ls1 += __shfl_xor_sync(0xffffffffu, ls1, 1);
        ls1 += __shfl_xor_sync(0xffffffffu, ls1, 2);

        l0 = l0 * a0 + ls0; m0r = mn0;
        l1 = l1 * a1 + ls1; m1r = mn1;
#pragma unroll
        for (int nt = 0; nt < 8; nt++) {
            o[nt][0] *= a0; o[nt][1] *= a0;
            o[nt][2] *= a1; o[nt][3] *= a1;
        }

        // P -> smem as tf32 (per-warp private rows: only __syncwarp)
#pragma unroll
        for (int nt = 0; nt < 8; nt++) {
            const int cc = nt * 8 + 2 * tig;
            *(uint2*)&Ps[rw * KROW + cc] =
                make_uint2(f2tf(s[nt][0]), f2tf(s[nt][1]));
            *(uint2*)&Ps[(rw + 8) * KROW + cc] =
                make_uint2(f2tf(s[nt][2]), f2tf(s[nt][3]));
        }
        __syncwarp();

        // O += P V  (16 x 64 per warp)
#pragma unroll
        for (int kc = 0; kc < 8; kc++) {
            const int kb = kc * 8;
            unsigned pa[4];
            pa[0] = Ps[rw * KROW + kb + tig];
            pa[1] = Ps[(rw + 8) * KROW + kb + tig];
            pa[2] = Ps[rw * KROW + kb + tig + 4];
            pa[3] = Ps[(rw + 8) * KROW + kb + tig + 4];
#pragma unroll
            for (int nt = 0; nt < 8; nt++) {
                unsigned bb[2];
                bb[0] = Vs[(kb + tig) * VROW + nt * 8 + gid];
                bb[1] = Vs[(kb + tig + 4) * VROW + nt * 8 + gid];
                mma_tf32(o[nt], pa, bb);
            }
        }
    }

    // epilogue (f32 out)
    const float inv0 = 1.f / l0;
    const float inv1 = 1.f / l1;
    const size_t r0 = (size_t)(b * TT + q0 + rw) * CDIM + h * DD;
    const size_t r1 = (size_t)(b * TT + q0 + rw + 8) * CDIM + h * DD;
#pragma unroll
    for (int nt = 0; nt < 8; nt++) {
        const int cc = nt * 8 + 2 * tig;
        *(float2*)&ctx[r0 + cc] = make_float2(o[nt][0] * inv0, o[nt][1] * inv0);
        *(float2*)&ctx[r1 + cc] = make_float2(o[nt][2] * inv1, o[nt][3] * inv1);
    }
}

// ---------------------------------------------------------------------------
extern "C" void kernel_launch(void* const* d_in, const int* in_sizes, int n_in,
                              void* d_out, int out_size) {
    const float* x  = (const float*)d_in[0];
    const float* wq = (const float*)d_in[1];
    const float* wk = (const float*)d_in[2];
    const float* wv = (const float*)d_in[3];
    const float* wo = (const float*)d_in[4];
    float* out = (float*)d_out;

    float* q;   cudaGetSymbolAddress((void**)&q,   g_q);
    float* kk;  cudaGetSymbolAddress((void**)&kk,  g_k);
    float* v;   cudaGetSymbolAddress((void**)&v,   g_v);
    float* ctx; cudaGetSymbolAddress((void**)&ctx, g_ctx);

    cudaFuncSetAttribute(attn_mma_kernel,
                         cudaFuncAttributeMaxDynamicSharedMemorySize, ATTN_SMEM);

    dim3 gg(CDIM / 128, BT / 128);
    // Q pre-scaled by 1/sqrt(D), written as tf32 bits
    gemm_mma_kernel<true><<<gg, 256>>>(x, wq, q, 0.125f);
    gemm_mma_kernel<true><<<gg, 256>>>(x, wk, kk, 1.0f);
    gemm_mma_kernel<true><<<gg, 256>>>(x, wv, v, 1.0f);

    dim3 ga(TT / 64, HH, BB);
    attn_mma_kernel<<<ga, 128, ATTN_SMEM>>>(q, kk, v, ctx);

    gemm_mma_kernel<false><<<gg, 256>>>(ctx, wo, out, 1.0f);
}

// round 8
// speedup vs baseline: 1.5791x; 1.0546x over previous
#include <cuda_runtime.h>
#include <cuda_bf16.h>
#include <cstdint>

#define BB 2
#define TT 4096
#define CDIM 768
#define HH 12
#define DD 64
#define BT (BB*TT)   // 8192

// Scratch (allocation-free rule: __device__ globals)
// q/k/v hold tf32 bit patterns (written by projection GEMMs); ctx is f32.
__device__ float g_q[BT*CDIM];
__device__ float g_k[BT*CDIM];
__device__ float g_v[BT*CDIM];
__device__ float g_ctx[BT*CDIM];

// ---------------------------------------------------------------------------
// helpers
// ---------------------------------------------------------------------------
__device__ __forceinline__ unsigned f2tf(float f) {
    unsigned u;
    asm("cvt.rna.tf32.f32 %0, %1;" : "=r"(u) : "f"(f));
    return u;
}

__device__ __forceinline__ void mma_tf32(float c[4], const unsigned a[4],
                                         const unsigned b[2]) {
    asm volatile(
        "mma.sync.aligned.m16n8k8.row.col.f32.tf32.tf32.f32 "
        "{%0,%1,%2,%3}, {%4,%5,%6,%7}, {%8,%9}, {%0,%1,%2,%3};\n"
        : "+f"(c[0]), "+f"(c[1]), "+f"(c[2]), "+f"(c[3])
        : "r"(a[0]), "r"(a[1]), "r"(a[2]), "r"(a[3]),
          "r"(b[0]), "r"(b[1]));
}

__device__ __forceinline__ void cp_async16(uint32_t saddr, const void* gptr) {
    asm volatile("cp.async.cg.shared.global [%0], [%1], 16;"
                 :: "r"(saddr), "l"(gptr));
}
__device__ __forceinline__ void cp_async_commit() {
    asm volatile("cp.async.commit_group;");
}
__device__ __forceinline__ void cp_async_wait0() {
    asm volatile("cp.async.wait_group 0;");
}

// ---------------------------------------------------------------------------
// GEMM core: computes one 128x128 tile of Y = X * W^T (tf32 mma, cp.async
// double-buffered BK=32). Shared by the fused-QKV kernel and the wo kernel.
// ---------------------------------------------------------------------------
template <bool TF32_OUT>
__device__ __forceinline__ void gemm_tile(
    const float* __restrict__ X, const float* __restrict__ W,
    float* __restrict__ Y, float out_scale,
    int m0, int n0,
    float (*As)[128][36], float (*Bs)[128][36]) {

    const int tid  = threadIdx.x;
    const int warp = tid >> 5;
    const int lane = tid & 31;
    const int gid  = lane >> 2;   // 0..7
    const int tig  = lane & 3;    // 0..3
    const int wm   = warp >> 2;   // 0..1
    const int wn   = warp & 3;    // 0..3

    const int lrow = tid >> 3;         // 0..31
    const int lcol = (tid & 7) * 4;    // 0..28

    const uint32_t a_sm[2] = {(uint32_t)__cvta_generic_to_shared(&As[0][0][0]),
                              (uint32_t)__cvta_generic_to_shared(&As[1][0][0])};
    const uint32_t b_sm[2] = {(uint32_t)__cvta_generic_to_shared(&Bs[0][0][0]),
                              (uint32_t)__cvta_generic_to_shared(&Bs[1][0][0])};

    float c[4][4][4];
#pragma unroll
    for (int mt = 0; mt < 4; mt++)
#pragma unroll
        for (int nt = 0; nt < 4; nt++)
#pragma unroll
            for (int i = 0; i < 4; i++) c[mt][nt][i] = 0.f;

    // prologue: stage 0 <- k0 = 0
#pragma unroll
    for (int i = 0; i < 4; i++) {
        cp_async16(a_sm[0] + (((lrow + i * 32) * 36 + lcol) * 4),
                   &X[(size_t)(m0 + lrow + i * 32) * CDIM + lcol]);
        cp_async16(b_sm[0] + (((lrow + i * 32) * 36 + lcol) * 4),
                   &W[(size_t)(n0 + lrow + i * 32) * CDIM + lcol]);
    }
    cp_async_commit();

    for (int k0 = 0; k0 < CDIM; k0 += 32) {
        const int s = (k0 >> 5) & 1;
        cp_async_wait0();
        __syncthreads();            // stage s visible; stage s^1 free

        if (k0 + 32 < CDIM) {
            const int ns = s ^ 1;
#pragma unroll
            for (int i = 0; i < 4; i++) {
                cp_async16(a_sm[ns] + (((lrow + i * 32) * 36 + lcol) * 4),
                           &X[(size_t)(m0 + lrow + i * 32) * CDIM + k0 + 32 + lcol]);
                cp_async16(b_sm[ns] + (((lrow + i * 32) * 36 + lcol) * 4),
                           &W[(size_t)(n0 + lrow + i * 32) * CDIM + k0 + 32 + lcol]);
            }
            cp_async_commit();
        }

#pragma unroll
        for (int ks = 0; ks < 4; ks++) {
            const int kb = ks * 8;
            unsigned a[4][4], b[4][2];
#pragma unroll
            for (int mt = 0; mt < 4; mt++) {
                const int r = wm * 64 + mt * 16 + gid;
                a[mt][0] = f2tf(As[s][r][kb + tig]);
                a[mt][1] = f2tf(As[s][r + 8][kb + tig]);
                a[mt][2] = f2tf(As[s][r][kb + tig + 4]);
                a[mt][3] = f2tf(As[s][r + 8][kb + tig + 4]);
            }
#pragma unroll
            for (int nt = 0; nt < 4; nt++) {
                const int rn = wn * 32 + nt * 8 + gid;
                b[nt][0] = f2tf(Bs[s][rn][kb + tig]);
                b[nt][1] = f2tf(Bs[s][rn][kb + tig + 4]);
            }
#pragma unroll
            for (int mt = 0; mt < 4; mt++)
#pragma unroll
                for (int nt = 0; nt < 4; nt++)
                    mma_tf32(c[mt][nt], a[mt], b[nt]);
        }
    }

#pragma unroll
    for (int mt = 0; mt < 4; mt++) {
        const int r = m0 + wm * 64 + mt * 16 + gid;
#pragma unroll
        for (int nt = 0; nt < 4; nt++) {
            const int cn = n0 + wn * 32 + nt * 8 + 2 * tig;
            if (TF32_OUT) {
                uint2 o01 = make_uint2(f2tf(c[mt][nt][0] * out_scale),
                                       f2tf(c[mt][nt][1] * out_scale));
                uint2 o23 = make_uint2(f2tf(c[mt][nt][2] * out_scale),
                                       f2tf(c[mt][nt][3] * out_scale));
                *(uint2*)&Y[(size_t)r * CDIM + cn]       = o01;
                *(uint2*)&Y[(size_t)(r + 8) * CDIM + cn] = o23;
            } else {
                *(float2*)&Y[(size_t)r * CDIM + cn] =
                    make_float2(c[mt][nt][0], c[mt][nt][1]);
                *(float2*)&Y[(size_t)(r + 8) * CDIM + cn] =
                    make_float2(c[mt][nt][2], c[mt][nt][3]);
            }
        }
    }
}

// Fused QKV projections: gridDim.z = 3 selects {wq->q, wk->k, wv->v}.
// One 1152-block launch -> ~3.9 waves @ 296 concurrent (~97% util) vs
// three 1.3-wave launches (~65%). X tiles get 3x L2 reuse.
__global__ __launch_bounds__(256) void gemm_qkv_kernel(
    const float* __restrict__ X,
    const float* __restrict__ wq, const float* __restrict__ wk,
    const float* __restrict__ wv,
    float* __restrict__ q, float* __restrict__ k, float* __restrict__ v) {
    __shared__ float As[2][128][36];
    __shared__ float Bs[2][128][36];

    const int z = blockIdx.z;
    const float* W = (z == 0) ? wq : (z == 1) ? wk : wv;
    float*       Y = (z == 0) ? q  : (z == 1) ? k  : v;
    const float scale = (z == 0) ? 0.125f : 1.0f;   // Q pre-scaled by 1/sqrt(D)

    gemm_tile<true>(X, W, Y, scale, blockIdx.y * 128, blockIdx.x * 128, As, Bs);
}

// Output projection: ctx * wo^T -> f32 out.
__global__ __launch_bounds__(256) void gemm_wo_kernel(
    const float* __restrict__ X, const float* __restrict__ W,
    float* __restrict__ Y) {
    __shared__ float As[2][128][36];
    __shared__ float Bs[2][128][36];
    gemm_tile<false>(X, W, Y, 1.0f, blockIdx.y * 128, blockIdx.x * 128, As, Bs);
}

// ---------------------------------------------------------------------------
// Flash attention (causal), tf32 mma, online softmax — EXACT 488us config.
// Separate P buffer, 69KB smem, 3 blocks/SM, serial K/V cp.async per tile,
// qt reversed. FROZEN (rounds 4-6 all regressed deviations).
// ---------------------------------------------------------------------------
#define KROW 68
#define VROW 72
#define ATTN_SMEM ((3 * 64 * KROW + 64 * VROW) * 4)

__global__ __launch_bounds__(128) void attn_mma_kernel(
    const float* __restrict__ q, const float* __restrict__ k,
    const float* __restrict__ v, float* __restrict__ ctx) {
    extern __shared__ unsigned sm[];
    unsigned* Qs = sm;
    unsigned* Ks = sm + 64 * KROW;
    unsigned* Ps = sm + 2 * 64 * KROW;
    unsigned* Vs = sm + 3 * 64 * KROW;

    const int tid  = threadIdx.x;
    const int warp = tid >> 5;
    const int lane = tid & 31;
    const int gid  = lane >> 2;
    const int tig  = lane & 3;
    const int rw   = warp * 16 + gid;    // this thread's first local row

    const int qt = gridDim.x - 1 - blockIdx.x;   // long blocks first
    const int h  = blockIdx.y;
    const int b  = blockIdx.z;
    const int q0 = qt * 64;

    const uint32_t qs_base = (uint32_t)__cvta_generic_to_shared(Qs);
    const uint32_t ks_base = (uint32_t)__cvta_generic_to_shared(Ks);
    const uint32_t vs_base = (uint32_t)__cvta_generic_to_shared(Vs);

    // Q tile: raw copy (already scaled tf32 bits)
    for (int e = tid; e < 1024; e += 128) {
        int rr = e >> 4, c4 = (e & 15) * 4;
        cp_async16(qs_base + (rr * KROW + c4) * 4,
                   &q[(size_t)(b * TT + q0 + rr) * CDIM + h * DD + c4]);
    }
    cp_async_commit();
    cp_async_wait0();
    __syncthreads();

    // Q fragments (held for the whole q-tile)
    unsigned qa[8][4];
#pragma unroll
    for (int ks = 0; ks < 8; ks++) {
        qa[ks][0] = Qs[rw * KROW + ks * 8 + tig];
        qa[ks][1] = Qs[(rw + 8) * KROW + ks * 8 + tig];
        qa[ks][2] = Qs[rw * KROW + ks * 8 + tig + 4];
        qa[ks][3] = Qs[(rw + 8) * KROW + ks * 8 + tig + 4];
    }

    float o[8][4];
#pragma unroll
    for (int nt = 0; nt < 8; nt++)
#pragma unroll
        for (int i = 0; i < 4; i++) o[nt][i] = 0.f;
    float m0r = -1e30f, m1r = -1e30f, l0 = 0.f, l1 = 0.f;

    for (int jt = 0; jt <= qt; jt++) {
        __syncthreads();   // prior compute done before smem overwrite
        for (int e = tid; e < 1024; e += 128) {
            int rr = e >> 4, c4 = (e & 15) * 4;
            size_t gbase = (size_t)(b * TT + jt * 64 + rr) * CDIM + h * DD + c4;
            cp_async16(ks_base + (rr * KROW + c4) * 4, &k[gbase]);
            cp_async16(vs_base + (rr * VROW + c4) * 4, &v[gbase]);
        }
        cp_async_commit();
        cp_async_wait0();
        __syncthreads();

        // S = Q K^T  (16 x 64 per warp)
        float s[8][4];
#pragma unroll
        for (int nt = 0; nt < 8; nt++)
#pragma unroll
            for (int i = 0; i < 4; i++) s[nt][i] = 0.f;

#pragma unroll
        for (int ks = 0; ks < 8; ks++) {
            const int kb = ks * 8;
#pragma unroll
            for (int nt = 0; nt < 8; nt++) {
                unsigned bb[2];
                const int rn = nt * 8 + gid;
                bb[0] = Ks[rn * KROW + kb + tig];
                bb[1] = Ks[rn * KROW + kb + tig + 4];
                mma_tf32(s[nt], qa[ks], bb);
            }
        }

        // causal mask (diagonal tile only)
        if (jt == qt) {
#pragma unroll
            for (int nt = 0; nt < 8; nt++) {
                const int cg = nt * 8 + 2 * tig;
                if (cg > rw)         s[nt][0] = -1e30f;
                if (cg + 1 > rw)     s[nt][1] = -1e30f;
                if (cg > rw + 8)     s[nt][2] = -1e30f;
                if (cg + 1 > rw + 8) s[nt][3] = -1e30f;
            }
        }

        // row maxima (two rows per thread)
        float mx0 = -1e30f, mx1 = -1e30f;
#pragma unroll
        for (int nt = 0; nt < 8; nt++) {
            mx0 = fmaxf(mx0, fmaxf(s[nt][0], s[nt][1]));
            mx1 = fmaxf(mx1, fmaxf(s[nt][2], s[nt][3]));
        }
        mx0 = fmaxf(mx0, __shfl_xor_sync(0xffffffffu, mx0, 1));
        mx0 = fmaxf(mx0, __shfl_xor_sync(0xffffffffu, mx0, 2));
        mx1 = fmaxf(mx1, __shfl_xor_sync(0xffffffffu, mx1, 1));
        mx1 = fmaxf(mx1, __shfl_xor_sync(0xffffffffu, mx1, 2));

        const float mn0 = fmaxf(m0r, mx0);
        const float mn1 = fmaxf(m1r, mx1);
        const float a0 = __expf(m0r - mn0);
        const float a1 = __expf(m1r - mn1);

        float ls0 = 0.f, ls1 = 0.f;
#pragma unroll
        for (int nt = 0; nt < 8; nt++) {
            s[nt][0] = __expf(s[nt][0] - mn0); ls0 += s[nt][0];
            s[nt][1] = __expf(s[nt][1] - mn0); ls0 += s[nt][1];
            s[nt][2] = __expf(s[nt][2] - mn1); ls1 += s[nt][2];
            s[nt][3] = __expf(s[nt][3] - mn1); ls1 += s[nt][3];
        }
        ls0 += __shfl_xor_sync(0xffffffffu, ls0, 1);
        ls0 += __shfl_xor_sync(0xffffffffu, ls0, 2);
        ls1 += __shfl_xor_sync(0xffffffffu, ls1, 1);
        ls1 += __shfl_xor_sync(0xffffffffu, ls1, 2);

        l0 = l0 * a0 + ls0; m0r = mn0;
        l1 = l1 * a1 + ls1; m1r = mn1;
#pragma unroll
        for (int nt = 0; nt < 8; nt++) {
            o[nt][0] *= a0; o[nt][1] *= a0;
            o[nt][2] *= a1; o[nt][3] *= a1;
        }

        // P -> smem as tf32 (per-warp private rows: only __syncwarp)
#pragma unroll
        for (int nt = 0; nt < 8; nt++) {
            const int cc = nt * 8 + 2 * tig;
            *(uint2*)&Ps[rw * KROW + cc] =
                make_uint2(f2tf(s[nt][0]), f2tf(s[nt][1]));
            *(uint2*)&Ps[(rw + 8) * KROW + cc] =
                make_uint2(f2tf(s[nt][2]), f2tf(s[nt][3]));
        }
        __syncwarp();

        // O += P V  (16 x 64 per warp)
#pragma unroll
        for (int kc = 0; kc < 8; kc++) {
            const int kb = kc * 8;
            unsigned pa[4];
            pa[0] = Ps[rw * KROW + kb + tig];
            pa[1] = Ps[(rw + 8) * KROW + kb + tig];
            pa[2] = Ps[rw * KROW + kb + tig + 4];
            pa[3] = Ps[(rw + 8) * KROW + kb + tig + 4];
#pragma unroll
            for (int nt = 0; nt < 8; nt++) {
                unsigned bb[2];
                bb[0] = Vs[(kb + tig) * VROW + nt * 8 + gid];
                bb[1] = Vs[(kb + tig + 4) * VROW + nt * 8 + gid];
                mma_tf32(o[nt], pa, bb);
            }
        }
    }

    // epilogue (f32 out)
    const float inv0 = 1.f / l0;
    const float inv1 = 1.f / l1;
    const size_t r0 = (size_t)(b * TT + q0 + rw) * CDIM + h * DD;
    const size_t r1 = (size_t)(b * TT + q0 + rw + 8) * CDIM + h * DD;
#pragma unroll
    for (int nt = 0; nt < 8; nt++) {
        const int cc = nt * 8 + 2 * tig;
        *(float2*)&ctx[r0 + cc] = make_float2(o[nt][0] * inv0, o[nt][1] * inv0);
        *(float2*)&ctx[r1 + cc] = make_float2(o[nt][2] * inv1, o[nt][3] * inv1);
    }
}

// ---------------------------------------------------------------------------
extern "C" void kernel_launch(void* const* d_in, const int* in_sizes, int n_in,
                              void* d_out, int out_size) {
    const float* x  = (const float*)d_in[0];
    const float* wq = (const float*)d_in[1];
    const float* wk = (const float*)d_in[2];
    const float* wv = (const float*)d_in[3];
    const float* wo = (const float*)d_in[4];
    float* out = (float*)d_out;

    float* q;   cudaGetSymbolAddress((void**)&q,   g_q);
    float* kk;  cudaGetSymbolAddress((void**)&kk,  g_k);
    float* v;   cudaGetSymbolAddress((void**)&v,   g_v);
    float* ctx; cudaGetSymbolAddress((void**)&ctx, g_ctx);

    cudaFuncSetAttribute(attn_mma_kernel,
                         cudaFuncAttributeMaxDynamicSharedMemorySize, ATTN_SMEM);

    // Fused QKV projections (one launch, 1152 blocks)
    dim3 gq(CDIM / 128, BT / 128, 3);
    gemm_qkv_kernel<<<gq, 256>>>(x, wq, wk, wv, q, kk, v);

    dim3 ga(TT / 64, HH, BB);
    attn_mma_kernel<<<ga, 128, ATTN_SMEM>>>(q, kk, v, ctx);

    dim3 gg(CDIM / 128, BT / 128);
    gemm_wo_kernel<<<gg, 256>>>(ctx, wo, out);
}

// round 9
// speedup vs baseline: 2.8553x; 1.8082x over previous
#include <cuda_runtime.h>
#include <cuda_fp16.h>
#include <cstdint>

#define BB 2
#define TT 4096
#define CDIM 768
#define HH 12
#define DD 64
#define BT (BB*TT)   // 8192

// Scratch (allocation-free rule: __device__ globals)
__device__ __half g_xh[BT*CDIM];          // x in fp16
__device__ __half g_wqh[CDIM*CDIM];
__device__ __half g_wkh[CDIM*CDIM];
__device__ __half g_wvh[CDIM*CDIM];
__device__ __half g_woh[CDIM*CDIM];
__device__ __half g_qh[BT*CDIM];          // Q (pre-scaled) fp16 [BT][C]
__device__ __half g_kh[BT*CDIM];          // K fp16 [BT][C]
__device__ __half g_vt[BB*CDIM*TT];       // V fp16 transposed: [(b*C + h*64+d)][t]
__device__ __half g_ctxh[BT*CDIM];        // attention output fp16

// ---------------------------------------------------------------------------
// helpers
// ---------------------------------------------------------------------------
__device__ __forceinline__ void mma_f16(float c[4], const unsigned a[4],
                                        const unsigned b[2]) {
    asm volatile(
        "mma.sync.aligned.m16n8k16.row.col.f32.f16.f16.f32 "
        "{%0,%1,%2,%3}, {%4,%5,%6,%7}, {%8,%9}, {%0,%1,%2,%3};\n"
        : "+f"(c[0]), "+f"(c[1]), "+f"(c[2]), "+f"(c[3])
        : "r"(a[0]), "r"(a[1]), "r"(a[2]), "r"(a[3]),
          "r"(b[0]), "r"(b[1]));
}

__device__ __forceinline__ void cp_async16(uint32_t saddr, const void* gptr) {
    asm volatile("cp.async.cg.shared.global [%0], [%1], 16;"
                 :: "r"(saddr), "l"(gptr));
}
__device__ __forceinline__ void cp_async_commit() {
    asm volatile("cp.async.commit_group;");
}
__device__ __forceinline__ void cp_async_wait0() {
    asm volatile("cp.async.wait_group 0;");
}

// ---------------------------------------------------------------------------
// f32 -> f16 elementwise (vectorized): one-time input conversion
// ---------------------------------------------------------------------------
__global__ __launch_bounds__(256) void f32_to_f16_kernel(
    const float* __restrict__ src, __half* __restrict__ dst, int n4) {
    int i = blockIdx.x * blockDim.x + threadIdx.x;
    if (i < n4) {
        float4 f = ((const float4*)src)[i];
        __half2 h0 = __floats2half2_rn(f.x, f.y);
        __half2 h1 = __floats2half2_rn(f.z, f.w);
        ((__half2*)dst)[2 * i]     = h0;
        ((__half2*)dst)[2 * i + 1] = h1;
    }
}

// ---------------------------------------------------------------------------
// fp16 GEMM core: one 128x128 tile of Y = X * W^T.
// Block 128x128, BK=32 (2 fp16 k-steps), cp.async double-buffered,
// 256 thr = 8 warps (2M x 4N), warp tile 64x32.
// OUT_MODE: 0 = fp16 [BT][C] scaled, 1 = fp16 V-transposed, 2 = f32 [BT][C].
// ---------------------------------------------------------------------------
__device__ __forceinline__ void gemm_tile_f16(
    const __half* __restrict__ X, const __half* __restrict__ W,
    void* __restrict__ Yv, float out_scale, int out_mode,
    int m0, int n0, __half (*As)[128][40], __half (*Bs)[128][40]) {

    const int tid  = threadIdx.x;
    const int warp = tid >> 5;
    const int lane = tid & 31;
    const int gid  = lane >> 2;   // 0..7
    const int tig  = lane & 3;    // 0..3
    const int wm   = warp >> 2;   // 0..1
    const int wn   = warp & 3;    // 0..3

    const int lrow = tid >> 2;         // 0..63
    const int lch  = (tid & 3) * 8;    // half offset 0,8,16,24

    const uint32_t a_sm[2] = {(uint32_t)__cvta_generic_to_shared(&As[0][0][0]),
                              (uint32_t)__cvta_generic_to_shared(&As[1][0][0])};
    const uint32_t b_sm[2] = {(uint32_t)__cvta_generic_to_shared(&Bs[0][0][0]),
                              (uint32_t)__cvta_generic_to_shared(&Bs[1][0][0])};

    float c[4][4][4];
#pragma unroll
    for (int mt = 0; mt < 4; mt++)
#pragma unroll
        for (int nt = 0; nt < 4; nt++)
#pragma unroll
            for (int i = 0; i < 4; i++) c[mt][nt][i] = 0.f;

    // prologue: stage 0 <- k0 = 0
#pragma unroll
    for (int i = 0; i < 2; i++) {
        const int r = lrow + i * 64;
        cp_async16(a_sm[0] + (r * 40 + lch) * 2,
                   &X[(size_t)(m0 + r) * CDIM + lch]);
        cp_async16(b_sm[0] + (r * 40 + lch) * 2,
                   &W[(size_t)(n0 + r) * CDIM + lch]);
    }
    cp_async_commit();

    for (int k0 = 0; k0 < CDIM; k0 += 32) {
        const int s = (k0 >> 5) & 1;
        cp_async_wait0();
        __syncthreads();

        if (k0 + 32 < CDIM) {
            const int ns = s ^ 1;
#pragma unroll
            for (int i = 0; i < 2; i++) {
                const int r = lrow + i * 64;
                cp_async16(a_sm[ns] + (r * 40 + lch) * 2,
                           &X[(size_t)(m0 + r) * CDIM + k0 + 32 + lch]);
                cp_async16(b_sm[ns] + (r * 40 + lch) * 2,
                           &W[(size_t)(n0 + r) * CDIM + k0 + 32 + lch]);
            }
            cp_async_commit();
        }

#pragma unroll
        for (int ks = 0; ks < 2; ks++) {
            const int kb = ks * 16;
            unsigned a[4][4], b[4][2];
#pragma unroll
            for (int mt = 0; mt < 4; mt++) {
                const int r = wm * 64 + mt * 16 + gid;
                a[mt][0] = *(const unsigned*)&As[s][r][kb + 2 * tig];
                a[mt][1] = *(const unsigned*)&As[s][r + 8][kb + 2 * tig];
                a[mt][2] = *(const unsigned*)&As[s][r][kb + 2 * tig + 8];
                a[mt][3] = *(const unsigned*)&As[s][r + 8][kb + 2 * tig + 8];
            }
#pragma unroll
            for (int nt = 0; nt < 4; nt++) {
                const int rn = wn * 32 + nt * 8 + gid;
                b[nt][0] = *(const unsigned*)&Bs[s][rn][kb + 2 * tig];
                b[nt][1] = *(const unsigned*)&Bs[s][rn][kb + 2 * tig + 8];
            }
#pragma unroll
            for (int mt = 0; mt < 4; mt++)
#pragma unroll
                for (int nt = 0; nt < 4; nt++)
                    mma_f16(c[mt][nt], a[mt], b[nt]);
        }
    }

    // epilogue
#pragma unroll
    for (int mt = 0; mt < 4; mt++) {
        const int gr = m0 + wm * 64 + mt * 16 + gid;   // global row (token)
#pragma unroll
        for (int nt = 0; nt < 4; nt++) {
            const int cn = n0 + wn * 32 + nt * 8 + 2 * tig;
            if (out_mode == 0) {
                __half* Y = (__half*)Yv;
                *(__half2*)&Y[(size_t)gr * CDIM + cn] =
                    __floats2half2_rn(c[mt][nt][0] * out_scale,
                                      c[mt][nt][1] * out_scale);
                *(__half2*)&Y[(size_t)(gr + 8) * CDIM + cn] =
                    __floats2half2_rn(c[mt][nt][2] * out_scale,
                                      c[mt][nt][3] * out_scale);
            } else if (out_mode == 1) {
                // V transposed: vt[(b*C + cn)][t],  gr = b*TT + t
                __half* Y = (__half*)Yv;
                const int bi = gr >> 12;         // /TT
                const int t  = gr & (TT - 1);
                const size_t base = (size_t)bi * CDIM * TT;
                Y[base + (size_t)cn * TT + t]           = __float2half(c[mt][nt][0]);
                Y[base + (size_t)(cn + 1) * TT + t]     = __float2half(c[mt][nt][1]);
                Y[base + (size_t)cn * TT + t + 8]       = __float2half(c[mt][nt][2]);
                Y[base + (size_t)(cn + 1) * TT + t + 8] = __float2half(c[mt][nt][3]);
            } else {
                float* Y = (float*)Yv;
                *(float2*)&Y[(size_t)gr * CDIM + cn] =
                    make_float2(c[mt][nt][0], c[mt][nt][1]);
                *(float2*)&Y[(size_t)(gr + 8) * CDIM + cn] =
                    make_float2(c[mt][nt][2], c[mt][nt][3]);
            }
        }
    }
}

// Fused QKV: gridDim.z = 3 selects {wq->qh(x0.125), wk->kh, wv->vt}.
__global__ __launch_bounds__(256) void gemm_qkv_kernel(
    const __half* __restrict__ X,
    const __half* __restrict__ wq, const __half* __restrict__ wk,
    const __half* __restrict__ wv,
    __half* __restrict__ q, __half* __restrict__ k, __half* __restrict__ vt) {
    __shared__ __half As[2][128][40];
    __shared__ __half Bs[2][128][40];

    const int z = blockIdx.z;
    const __half* W = (z == 0) ? wq : (z == 1) ? wk : wv;
    void*         Y = (z == 0) ? (void*)q : (z == 1) ? (void*)k : (void*)vt;
    const float scale = (z == 0) ? 0.125f : 1.0f;
    const int mode = (z == 2) ? 1 : 0;

    gemm_tile_f16(X, W, Y, scale, mode, blockIdx.y * 128, blockIdx.x * 128, As, Bs);
}

// Output projection: ctxh * wo^T -> f32 out.
__global__ __launch_bounds__(256) void gemm_wo_kernel(
    const __half* __restrict__ X, const __half* __restrict__ W,
    float* __restrict__ Y) {
    __shared__ __half As[2][128][40];
    __shared__ __half Bs[2][128][40];
    gemm_tile_f16(X, W, Y, 1.0f, 2, blockIdx.y * 128, blockIdx.x * 128, As, Bs);
}

// ---------------------------------------------------------------------------
// Flash attention (causal), fp16 mma k16, online softmax.
// SAME loop structure as the proven 488us kernel: serial K/V cp.async per
// tile, wait0, 2 syncthreads/iter, qt reversed, separate P buffer.
// All tiles fp16, rows padded to 72 halves (conflict-free half2 patterns).
// V is consumed from the pre-transposed vt buffer -> PV b-frags contiguous.
// ---------------------------------------------------------------------------
#define ROWH 72
#define ATTN_SMEM (4 * 64 * ROWH * 2)

__global__ __launch_bounds__(128) void attn_mma_kernel(
    const __half* __restrict__ q, const __half* __restrict__ k,
    const __half* __restrict__ vt, __half* __restrict__ ctx) {
    extern __shared__ __half smh[];
    __half* Qs  = smh;
    __half* Ks  = smh + 64 * ROWH;
    __half* Ps  = smh + 2 * 64 * ROWH;
    __half* VTs = smh + 3 * 64 * ROWH;   // [d][key]

    const int tid  = threadIdx.x;
    const int warp = tid >> 5;
    const int lane = tid & 31;
    const int gid  = lane >> 2;
    const int tig  = lane & 3;
    const int rw   = warp * 16 + gid;    // this thread's first local row

    const int qt = gridDim.x - 1 - blockIdx.x;   // long blocks first
    const int h  = blockIdx.y;
    const int b  = blockIdx.z;
    const int q0 = qt * 64;

    const uint32_t qs_base = (uint32_t)__cvta_generic_to_shared(Qs);
    const uint32_t ks_base = (uint32_t)__cvta_generic_to_shared(Ks);
    const uint32_t vs_base = (uint32_t)__cvta_generic_to_shared(VTs);

    // Q tile (fp16, pre-scaled): 64 rows x 128B
    for (int e = tid; e < 512; e += 128) {
        int rr = e >> 3, c8 = (e & 7) * 8;
        cp_async16(qs_base + (rr * ROWH + c8) * 2,
                   &q[(size_t)(b * TT + q0 + rr) * CDIM + h * DD + c8]);
    }
    cp_async_commit();
    cp_async_wait0();
    __syncthreads();

    // Q fragments (k16 x 4 steps), half2 packed
    unsigned qa[4][4];
#pragma unroll
    for (int ks = 0; ks < 4; ks++) {
        const int kb = ks * 16;
        qa[ks][0] = *(const unsigned*)&Qs[rw * ROWH + kb + 2 * tig];
        qa[ks][1] = *(const unsigned*)&Qs[(rw + 8) * ROWH + kb + 2 * tig];
        qa[ks][2] = *(const unsigned*)&Qs[rw * ROWH + kb + 2 * tig + 8];
        qa[ks][3] = *(const unsigned*)&Qs[(rw + 8) * ROWH + kb + 2 * tig + 8];
    }

    float o[8][4];
#pragma unroll
    for (int nt = 0; nt < 8; nt++)
#pragma unroll
        for (int i = 0; i < 4; i++) o[nt][i] = 0.f;
    float m0r = -1e30f, m1r = -1e30f, l0 = 0.f, l1 = 0.f;

    for (int jt = 0; jt <= qt; jt++) {
        __syncthreads();   // prior compute done before smem overwrite
        for (int e = tid; e < 512; e += 128) {
            int rr = e >> 3, c8 = (e & 7) * 8;
            cp_async16(ks_base + (rr * ROWH + c8) * 2,
                       &k[(size_t)(b * TT + jt * 64 + rr) * CDIM + h * DD + c8]);
            cp_async16(vs_base + (rr * ROWH + c8) * 2,
                       &vt[(size_t)(b * CDIM + h * DD + rr) * TT + jt * 64 + c8]);
        }
        cp_async_commit();
        cp_async_wait0();
        __syncthreads();

        // S = Q K^T  (16 x 64 per warp), 4 k-steps of 16
        float s[8][4];
#pragma unroll
        for (int nt = 0; nt < 8; nt++)
#pragma unroll
            for (int i = 0; i < 4; i++) s[nt][i] = 0.f;

#pragma unroll
        for (int ks = 0; ks < 4; ks++) {
            const int kb = ks * 16;
#pragma unroll
            for (int nt = 0; nt < 8; nt++) {
                const int rn = nt * 8 + gid;
                unsigned bb[2];
                bb[0] = *(const unsigned*)&Ks[rn * ROWH + kb + 2 * tig];
                bb[1] = *(const unsigned*)&Ks[rn * ROWH + kb + 2 * tig + 8];
                mma_f16(s[nt], qa[ks], bb);
            }
        }

        // causal mask (diagonal tile only)
        if (jt == qt) {
#pragma unroll
            for (int nt = 0; nt < 8; nt++) {
                const int cg = nt * 8 + 2 * tig;
                if (cg > rw)         s[nt][0] = -1e30f;
                if (cg + 1 > rw)     s[nt][1] = -1e30f;
                if (cg > rw + 8)     s[nt][2] = -1e30f;
                if (cg + 1 > rw + 8) s[nt][3] = -1e30f;
            }
        }

        // row maxima (two rows per thread)
        float mx0 = -1e30f, mx1 = -1e30f;
#pragma unroll
        for (int nt = 0; nt < 8; nt++) {
            mx0 = fmaxf(mx0, fmaxf(s[nt][0], s[nt][1]));
            mx1 = fmaxf(mx1, fmaxf(s[nt][2], s[nt][3]));
        }
        mx0 = fmaxf(mx0, __shfl_xor_sync(0xffffffffu, mx0, 1));
        mx0 = fmaxf(mx0, __shfl_xor_sync(0xffffffffu, mx0, 2));
        mx1 = fmaxf(mx1, __shfl_xor_sync(0xffffffffu, mx1, 1));
        mx1 = fmaxf(mx1, __shfl_xor_sync(0xffffffffu, mx1, 2));

        const float mn0 = fmaxf(m0r, mx0);
        const float mn1 = fmaxf(m1r, mx1);
        const float a0 = __expf(m0r - mn0);
        const float a1 = __expf(m1r - mn1);

        float ls0 = 0.f, ls1 = 0.f;
#pragma unroll
        for (int nt = 0; nt < 8; nt++) {
            s[nt][0] = __expf(s[nt][0] - mn0); ls0 += s[nt][0];
            s[nt][1] = __expf(s[nt][1] - mn0); ls0 += s[nt][1];
            s[nt][2] = __expf(s[nt][2] - mn1); ls1 += s[nt][2];
            s[nt][3] = __expf(s[nt][3] - mn1); ls1 += s[nt][3];
        }
        ls0 += __shfl_xor_sync(0xffffffffu, ls0, 1);
        ls0 += __shfl_xor_sync(0xffffffffu, ls0, 2);
        ls1 += __shfl_xor_sync(0xffffffffu, ls1, 1);
        ls1 += __shfl_xor_sync(0xffffffffu, ls1, 2);

        l0 = l0 * a0 + ls0; m0r = mn0;
        l1 = l1 * a1 + ls1; m1r = mn1;
#pragma unroll
        for (int nt = 0; nt < 8; nt++) {
            o[nt][0] *= a0; o[nt][1] *= a0;
            o[nt][2] *= a1; o[nt][3] *= a1;
        }

        // P -> smem fp16 (warp-private 16-row band: __syncwarp only)
#pragma unroll
        for (int nt = 0; nt < 8; nt++) {
            const int cc = nt * 8 + 2 * tig;
            *(__half2*)&Ps[rw * ROWH + cc] =
                __floats2half2_rn(s[nt][0], s[nt][1]);
            *(__half2*)&Ps[(rw + 8) * ROWH + cc] =
                __floats2half2_rn(s[nt][2], s[nt][3]);
        }
        __syncwarp();

        // O += P V  (16 x 64 per warp), 4 k-steps of 16; b from VTs[d][key]
#pragma unroll
        for (int kc = 0; kc < 4; kc++) {
            const int kb = kc * 16;
            unsigned pa[4];
            pa[0] = *(const unsigned*)&Ps[rw * ROWH + kb + 2 * tig];
            pa[1] = *(const unsigned*)&Ps[(rw + 8) * ROWH + kb + 2 * tig];
            pa[2] = *(const unsigned*)&Ps[rw * ROWH + kb + 2 * tig + 8];
            pa[3] = *(const unsigned*)&Ps[(rw + 8) * ROWH + kb + 2 * tig + 8];
#pragma unroll
            for (int nt = 0; nt < 8; nt++) {
                const int rn = nt * 8 + gid;
                unsigned bb[2];
                bb[0] = *(const unsigned*)&VTs[rn * ROWH + kb + 2 * tig];
                bb[1] = *(const unsigned*)&VTs[rn * ROWH + kb + 2 * tig + 8];
                mma_f16(o[nt], pa, bb);
            }
        }
    }

    // epilogue -> fp16 ctx
    const float inv0 = 1.f / l0;
    const float inv1 = 1.f / l1;
    const size_t r0 = (size_t)(b * TT + q0 + rw) * CDIM + h * DD;
    const size_t r1 = (size_t)(b * TT + q0 + rw + 8) * CDIM + h * DD;
#pragma unroll
    for (int nt = 0; nt < 8; nt++) {
        const int cc = nt * 8 + 2 * tig;
        *(__half2*)&ctx[r0 + cc] =
            __floats2half2_rn(o[nt][0] * inv0, o[nt][1] * inv0);
        *(__half2*)&ctx[r1 + cc] =
            __floats2half2_rn(o[nt][2] * inv1, o[nt][3] * inv1);
    }
}

// ---------------------------------------------------------------------------
extern "C" void kernel_launch(void* const* d_in, const int* in_sizes, int n_in,
                              void* d_out, int out_size) {
    const float* x  = (const float*)d_in[0];
    const float* wq = (const float*)d_in[1];
    const float* wk = (const float*)d_in[2];
    const float* wv = (const float*)d_in[3];
    const float* wo = (const float*)d_in[4];
    float* out = (float*)d_out;

    __half *xh, *wqh, *wkh, *wvh, *woh, *qh, *kh, *vt, *ctxh;
    cudaGetSymbolAddress((void**)&xh,   g_xh);
    cudaGetSymbolAddress((void**)&wqh,  g_wqh);
    cudaGetSymbolAddress((void**)&wkh,  g_wkh);
    cudaGetSymbolAddress((void**)&wvh,  g_wvh);
    cudaGetSymbolAddress((void**)&woh,  g_woh);
    cudaGetSymbolAddress((void**)&qh,   g_qh);
    cudaGetSymbolAddress((void**)&kh,   g_kh);
    cudaGetSymbolAddress((void**)&vt,   g_vt);
    cudaGetSymbolAddress((void**)&ctxh, g_ctxh);

    cudaFuncSetAttribute(attn_mma_kernel,
                         cudaFuncAttributeMaxDynamicSharedMemorySize, ATTN_SMEM);

    // one-time fp16 conversions
    const int nx4 = (BT * CDIM) / 4;
    const int nw4 = (CDIM * CDIM) / 4;
    f32_to_f16_kernel<<<(nx4 + 255) / 256, 256>>>(x,  xh,  nx4);
    f32_to_f16_kernel<<<(nw4 + 255) / 256, 256>>>(wq, wqh, nw4);
    f32_to_f16_kernel<<<(nw4 + 255) / 256, 256>>>(wk, wkh, nw4);
    f32_to_f16_kernel<<<(nw4 + 255) / 256, 256>>>(wv, wvh, nw4);
    f32_to_f16_kernel<<<(nw4 + 255) / 256, 256>>>(wo, woh, nw4);

    // fused QKV projections (fp16, V transposed per head)
    dim3 gq(CDIM / 128, BT / 128, 3);
    gemm_qkv_kernel<<<gq, 256>>>(xh, wqh, wkh, wvh, qh, kh, vt);

    dim3 ga(TT / 64, HH, BB);
    attn_mma_kernel<<<ga, 128, ATTN_SMEM>>>(qh, kh, vt, ctxh);

    dim3 gg(CDIM / 128, BT / 128);
    gemm_wo_kernel<<<gg, 256>>>(ctxh, woh, out);
}

// round 10
// speedup vs baseline: 3.1004x; 1.0859x over previous
#include <cuda_runtime.h>
#include <cuda_fp16.h>
#include <cstdint>

#define BB 2
#define TT 4096
#define CDIM 768
#define HH 12
#define DD 64
#define BT (BB*TT)   // 8192

// Scratch (allocation-free rule: __device__ globals)
__device__ __half g_xh[BT*CDIM];          // x in fp16
__device__ __half g_wqh[CDIM*CDIM];
__device__ __half g_wkh[CDIM*CDIM];
__device__ __half g_wvh[CDIM*CDIM];
__device__ __half g_woh[CDIM*CDIM];
__device__ __half g_qh[BT*CDIM];          // Q (pre-scaled) fp16 [BT][C]
__device__ __half g_kh[BT*CDIM];          // K fp16 [BT][C]
__device__ __half g_vt[BB*CDIM*TT];       // V fp16 transposed: [(b*C + h*64+d)][t]
__device__ __half g_ctxh[BT*CDIM];        // attention output fp16

// ---------------------------------------------------------------------------
// helpers
// ---------------------------------------------------------------------------
__device__ __forceinline__ void mma_f16(float c[4], const unsigned a[4],
                                        const unsigned b[2]) {
    asm volatile(
        "mma.sync.aligned.m16n8k16.row.col.f32.f16.f16.f32 "
        "{%0,%1,%2,%3}, {%4,%5,%6,%7}, {%8,%9}, {%0,%1,%2,%3};\n"
        : "+f"(c[0]), "+f"(c[1]), "+f"(c[2]), "+f"(c[3])
        : "r"(a[0]), "r"(a[1]), "r"(a[2]), "r"(a[3]),
          "r"(b[0]), "r"(b[1]));
}

__device__ __forceinline__ void ldsm_x4(unsigned& r0, unsigned& r1,
                                        unsigned& r2, unsigned& r3,
                                        uint32_t addr) {
    asm volatile("ldmatrix.sync.aligned.m8n8.x4.shared.b16 {%0,%1,%2,%3}, [%4];"
                 : "=r"(r0), "=r"(r1), "=r"(r2), "=r"(r3) : "r"(addr));
}

__device__ __forceinline__ void cp_async16(uint32_t saddr, const void* gptr) {
    asm volatile("cp.async.cg.shared.global [%0], [%1], 16;"
                 :: "r"(saddr), "l"(gptr));
}
__device__ __forceinline__ void cp_async_commit() {
    asm volatile("cp.async.commit_group;");
}
__device__ __forceinline__ void cp_async_wait0() {
    asm volatile("cp.async.wait_group 0;");
}

// ---------------------------------------------------------------------------
// One-shot f32 -> f16 conversion of x + 4 weight matrices (single launch)
// ---------------------------------------------------------------------------
__global__ __launch_bounds__(256) void convert_all_kernel(
    const float* __restrict__ x,  const float* __restrict__ wq,
    const float* __restrict__ wk, const float* __restrict__ wv,
    const float* __restrict__ wo,
    __half* __restrict__ xh,  __half* __restrict__ wqh,
    __half* __restrict__ wkh, __half* __restrict__ wvh,
    __half* __restrict__ woh) {
    const int NX = BT * CDIM / 4;
    const int NW = CDIM * CDIM / 4;
    int i = blockIdx.x * blockDim.x + threadIdx.x;
    const float* src; __half* dst; int j;
    if (i < NX) {
        src = x; dst = xh; j = i;
    } else {
        int t = i - NX;
        int seg = t / NW;
        if (seg > 3) return;
        j = t - seg * NW;
        src = (seg == 0) ? wq : (seg == 1) ? wk : (seg == 2) ? wv : wo;
        dst = (seg == 0) ? wqh : (seg == 1) ? wkh : (seg == 2) ? wvh : woh;
    }
    float4 f = ((const float4*)src)[j];
    ((__half2*)dst)[2 * j]     = __floats2half2_rn(f.x, f.y);
    ((__half2*)dst)[2 * j + 1] = __floats2half2_rn(f.z, f.w);
}

// ---------------------------------------------------------------------------
// fp16 GEMM core: one 128x128 tile of Y = X * W^T.
// Block 128x128, BK=32, cp.async double-buffered, 8 warps (2M x 4N),
// warp tile 64x32. Fragment loads via ldmatrix.x4.
// OUT_MODE: 0 = fp16 [BT][C] scaled, 1 = fp16 V-transposed, 2 = f32 [BT][C].
// ---------------------------------------------------------------------------
__device__ __forceinline__ void gemm_tile_f16(
    const __half* __restrict__ X, const __half* __restrict__ W,
    void* __restrict__ Yv, float out_scale, int out_mode,
    int m0, int n0, __half (*As)[128][40], __half (*Bs)[128][40]) {

    const int tid  = threadIdx.x;
    const int warp = tid >> 5;
    const int lane = tid & 31;
    const int gid  = lane >> 2;   // 0..7
    const int tig  = lane & 3;    // 0..3
    const int wm   = warp >> 2;   // 0..1
    const int wn   = warp & 3;    // 0..3

    const int lrow = tid >> 2;         // 0..63
    const int lch  = (tid & 3) * 8;    // half offset 0,8,16,24

    const uint32_t a_sm[2] = {(uint32_t)__cvta_generic_to_shared(&As[0][0][0]),
                              (uint32_t)__cvta_generic_to_shared(&As[1][0][0])};
    const uint32_t b_sm[2] = {(uint32_t)__cvta_generic_to_shared(&Bs[0][0][0]),
                              (uint32_t)__cvta_generic_to_shared(&Bs[1][0][0])};

    // ldmatrix lane offsets (bytes), row stride 40 halves
    const uint32_t a_loff =
        (((wm * 64 + (lane & 15)) * 40) + (lane >> 4) * 8) * 2;
    const uint32_t b_loff =
        ((((lane >> 4) * 8 + (lane & 7)) * 40) + ((lane >> 3) & 1) * 8) * 2;

    float c[4][4][4];
#pragma unroll
    for (int mt = 0; mt < 4; mt++)
#pragma unroll
        for (int nt = 0; nt < 4; nt++)
#pragma unroll
            for (int i = 0; i < 4; i++) c[mt][nt][i] = 0.f;

    // prologue: stage 0 <- k0 = 0
#pragma unroll
    for (int i = 0; i < 2; i++) {
        const int r = lrow + i * 64;
        cp_async16(a_sm[0] + (r * 40 + lch) * 2,
                   &X[(size_t)(m0 + r) * CDIM + lch]);
        cp_async16(b_sm[0] + (r * 40 + lch) * 2,
                   &W[(size_t)(n0 + r) * CDIM + lch]);
    }
    cp_async_commit();

    for (int k0 = 0; k0 < CDIM; k0 += 32) {
        const int s = (k0 >> 5) & 1;
        cp_async_wait0();
        __syncthreads();

        if (k0 + 32 < CDIM) {
            const int ns = s ^ 1;
#pragma unroll
            for (int i = 0; i < 2; i++) {
                const int r = lrow + i * 64;
                cp_async16(a_sm[ns] + (r * 40 + lch) * 2,
                           &X[(size_t)(m0 + r) * CDIM + k0 + 32 + lch]);
                cp_async16(b_sm[ns] + (r * 40 + lch) * 2,
                           &W[(size_t)(n0 + r) * CDIM + k0 + 32 + lch]);
            }
            cp_async_commit();
        }

#pragma unroll
        for (int ks = 0; ks < 2; ks++) {
            const int kb = ks * 16;
            unsigned a[4][4], b[4][2];
#pragma unroll
            for (int mt = 0; mt < 4; mt++)
                ldsm_x4(a[mt][0], a[mt][1], a[mt][2], a[mt][3],
                        a_sm[s] + a_loff + (mt * 16 * 40 + kb) * 2);
#pragma unroll
            for (int ntp = 0; ntp < 2; ntp++)
                ldsm_x4(b[2 * ntp][0], b[2 * ntp][1],
                        b[2 * ntp + 1][0], b[2 * ntp + 1][1],
                        b_sm[s] + b_loff + ((wn * 32 + ntp * 16) * 40 + kb) * 2);
#pragma unroll
            for (int mt = 0; mt < 4; mt++)
#pragma unroll
                for (int nt = 0; nt < 4; nt++)
                    mma_f16(c[mt][nt], a[mt], b[nt]);
        }
    }

    // epilogue
#pragma unroll
    for (int mt = 0; mt < 4; mt++) {
        const int gr = m0 + wm * 64 + mt * 16 + gid;   // global row (token)
#pragma unroll
        for (int nt = 0; nt < 4; nt++) {
            const int cn = n0 + wn * 32 + nt * 8 + 2 * tig;
            if (out_mode == 0) {
                __half* Y = (__half*)Yv;
                *(__half2*)&Y[(size_t)gr * CDIM + cn] =
                    __floats2half2_rn(c[mt][nt][0] * out_scale,
                                      c[mt][nt][1] * out_scale);
                *(__half2*)&Y[(size_t)(gr + 8) * CDIM + cn] =
                    __floats2half2_rn(c[mt][nt][2] * out_scale,
                                      c[mt][nt][3] * out_scale);
            } else if (out_mode == 1) {
                __half* Y = (__half*)Yv;
                const int bi = gr >> 12;
                const int t  = gr & (TT - 1);
                const size_t base = (size_t)bi * CDIM * TT;
                Y[base + (size_t)cn * TT + t]           = __float2half(c[mt][nt][0]);
                Y[base + (size_t)(cn + 1) * TT + t]     = __float2half(c[mt][nt][1]);
                Y[base + (size_t)cn * TT + t + 8]       = __float2half(c[mt][nt][2]);
                Y[base + (size_t)(cn + 1) * TT + t + 8] = __float2half(c[mt][nt][3]);
            } else {
                float* Y = (float*)Yv;
                *(float2*)&Y[(size_t)gr * CDIM + cn] =
                    make_float2(c[mt][nt][0], c[mt][nt][1]);
                *(float2*)&Y[(size_t)(gr + 8) * CDIM + cn] =
                    make_float2(c[mt][nt][2], c[mt][nt][3]);
            }
        }
    }
}

// Fused QKV: gridDim.z = 3 selects {wq->qh(x0.125), wk->kh, wv->vt}.
__global__ __launch_bounds__(256) void gemm_qkv_kernel(
    const __half* __restrict__ X,
    const __half* __restrict__ wq, const __half* __restrict__ wk,
    const __half* __restrict__ wv,
    __half* __restrict__ q, __half* __restrict__ k, __half* __restrict__ vt) {
    __shared__ __half As[2][128][40];
    __shared__ __half Bs[2][128][40];

    const int z = blockIdx.z;
    const __half* W = (z == 0) ? wq : (z == 1) ? wk : wv;
    void*         Y = (z == 0) ? (void*)q : (z == 1) ? (void*)k : (void*)vt;
    const float scale = (z == 0) ? 0.125f : 1.0f;
    const int mode = (z == 2) ? 1 : 0;

    gemm_tile_f16(X, W, Y, scale, mode, blockIdx.y * 128, blockIdx.x * 128, As, Bs);
}

// Output projection: ctxh * wo^T -> f32 out.
__global__ __launch_bounds__(256) void gemm_wo_kernel(
    const __half* __restrict__ X, const __half* __restrict__ W,
    float* __restrict__ Y) {
    __shared__ __half As[2][128][40];
    __shared__ __half Bs[2][128][40];
    gemm_tile_f16(X, W, Y, 1.0f, 2, blockIdx.y * 128, blockIdx.x * 128, As, Bs);
}

// ---------------------------------------------------------------------------
// Flash attention (causal), fp16 mma k16, online softmax.
// Proven loop structure (serial K/V cp.async per tile, wait0, 2 syncs/iter,
// qt reversed, separate P buffer). Fragment loads via ldmatrix.x4.
// ---------------------------------------------------------------------------
#define ROWH 72
#define ATTN_SMEM (4 * 64 * ROWH * 2)

__global__ __launch_bounds__(128) void attn_mma_kernel(
    const __half* __restrict__ q, const __half* __restrict__ k,
    const __half* __restrict__ vt, __half* __restrict__ ctx) {
    extern __shared__ __half smh[];
    __half* Qs  = smh;
    __half* Ks  = smh + 64 * ROWH;
    __half* Ps  = smh + 2 * 64 * ROWH;
    __half* VTs = smh + 3 * 64 * ROWH;   // [d][key]

    const int tid  = threadIdx.x;
    const int warp = tid >> 5;
    const int lane = tid & 31;
    const int gid  = lane >> 2;
    const int tig  = lane & 3;
    const int rw   = warp * 16 + gid;    // this thread's first local row

    const int qt = gridDim.x - 1 - blockIdx.x;   // long blocks first
    const int h  = blockIdx.y;
    const int b  = blockIdx.z;
    const int q0 = qt * 64;

    const uint32_t qs_base = (uint32_t)__cvta_generic_to_shared(Qs);
    const uint32_t ks_base = (uint32_t)__cvta_generic_to_shared(Ks);
    const uint32_t ps_base = (uint32_t)__cvta_generic_to_shared(Ps);
    const uint32_t vs_base = (uint32_t)__cvta_generic_to_shared(VTs);

    // ldmatrix lane offsets (bytes), row stride ROWH halves
    const uint32_t b_loff =
        ((((lane >> 4) * 8 + (lane & 7)) * ROWH) + ((lane >> 3) & 1) * 8) * 2;
    const uint32_t a_loff =
        (((warp * 16 + (lane & 15)) * ROWH) + (lane >> 4) * 8) * 2;

    // Q tile (fp16, pre-scaled): 64 rows x 128B
    for (int e = tid; e < 512; e += 128) {
        int rr = e >> 3, c8 = (e & 7) * 8;
        cp_async16(qs_base + (rr * ROWH + c8) * 2,
                   &q[(size_t)(b * TT + q0 + rr) * CDIM + h * DD + c8]);
    }
    cp_async_commit();
    cp_async_wait0();
    __syncthreads();

    // Q fragments (k16 x 4 steps) via ldmatrix
    unsigned qa[4][4];
#pragma unroll
    for (int ks = 0; ks < 4; ks++)
        ldsm_x4(qa[ks][0], qa[ks][1], qa[ks][2], qa[ks][3],
                qs_base + a_loff + (ks * 16) * 2);

    float o[8][4];
#pragma unroll
    for (int nt = 0; nt < 8; nt++)
#pragma unroll
        for (int i = 0; i < 4; i++) o[nt][i] = 0.f;
    float m0r = -1e30f, m1r = -1e30f, l0 = 0.f, l1 = 0.f;

    for (int jt = 0; jt <= qt; jt++) {
        __syncthreads();   // prior compute done before smem overwrite
        for (int e = tid; e < 512; e += 128) {
            int rr = e >> 3, c8 = (e & 7) * 8;
            cp_async16(ks_base + (rr * ROWH + c8) * 2,
                       &k[(size_t)(b * TT + jt * 64 + rr) * CDIM + h * DD + c8]);
            cp_async16(vs_base + (rr * ROWH + c8) * 2,
                       &vt[(size_t)(b * CDIM + h * DD + rr) * TT + jt * 64 + c8]);
        }
        cp_async_commit();
        cp_async_wait0();
        __syncthreads();

        // S = Q K^T  (16 x 64 per warp), 4 k-steps of 16
        float s[8][4];
#pragma unroll
        for (int nt = 0; nt < 8; nt++)
#pragma unroll
            for (int i = 0; i < 4; i++) s[nt][i] = 0.f;

#pragma unroll
        for (int ks = 0; ks < 4; ks++) {
            const int kb = ks * 16;
#pragma unroll
            for (int ntp = 0; ntp < 4; ntp++) {
                unsigned bb[2], bb2[2];
                ldsm_x4(bb[0], bb[1], bb2[0], bb2[1],
                        ks_base + b_loff + (ntp * 16 * ROWH + kb) * 2);
                mma_f16(s[2 * ntp],     qa[ks], bb);
                mma_f16(s[2 * ntp + 1], qa[ks], bb2);
            }
        }

        // causal mask (diagonal tile only)
        if (jt == qt) {
#pragma unroll
            for (int nt = 0; nt < 8; nt++) {
                const int cg = nt * 8 + 2 * tig;
                if (cg > rw)         s[nt][0] = -1e30f;
                if (cg + 1 > rw)     s[nt][1] = -1e30f;
                if (cg > rw + 8)     s[nt][2] = -1e30f;
                if (cg + 1 > rw + 8) s[nt][3] = -1e30f;
            }
        }

        // row maxima (two rows per thread)
        float mx0 = -1e30f, mx1 = -1e30f;
#pragma unroll
        for (int nt = 0; nt < 8; nt++) {
            mx0 = fmaxf(mx0, fmaxf(s[nt][0], s[nt][1]));
            mx1 = fmaxf(mx1, fmaxf(s[nt][2], s[nt][3]));
        }
        mx0 = fmaxf(mx0, __shfl_xor_sync(0xffffffffu, mx0, 1));
        mx0 = fmaxf(mx0, __shfl_xor_sync(0xffffffffu, mx0, 2));
        mx1 = fmaxf(mx1, __shfl_xor_sync(0xffffffffu, mx1, 1));
        mx1 = fmaxf(mx1, __shfl_xor_sync(0xffffffffu, mx1, 2));

        const float mn0 = fmaxf(m0r, mx0);
        const float mn1 = fmaxf(m1r, mx1);
        const float a0 = __expf(m0r - mn0);
        const float a1 = __expf(m1r - mn1);

        float ls0 = 0.f, ls1 = 0.f;
#pragma unroll
        for (int nt = 0; nt < 8; nt++) {
            s[nt][0] = __expf(s[nt][0] - mn0); ls0 += s[nt][0];
            s[nt][1] = __expf(s[nt][1] - mn0); ls0 += s[nt][1];
            s[nt][2] = __expf(s[nt][2] - mn1); ls1 += s[nt][2];
            s[nt][3] = __expf(s[nt][3] - mn1); ls1 += s[nt][3];
        }
        ls0 += __shfl_xor_sync(0xffffffffu, ls0, 1);
        ls0 += __shfl_xor_sync(0xffffffffu, ls0, 2);
        ls1 += __shfl_xor_sync(0xffffffffu, ls1, 1);
        ls1 += __shfl_xor_sync(0xffffffffu, ls1, 2);

        l0 = l0 * a0 + ls0; m0r = mn0;
        l1 = l1 * a1 + ls1; m1r = mn1;
#pragma unroll
        for (int nt = 0; nt < 8; nt++) {
            o[nt][0] *= a0; o[nt][1] *= a0;
            o[nt][2] *= a1; o[nt][3] *= a1;
        }

        // P -> smem fp16 (warp-private 16-row band: __syncwarp only)
#pragma unroll
        for (int nt = 0; nt < 8; nt++) {
            const int cc = nt * 8 + 2 * tig;
            *(__half2*)&Ps[rw * ROWH + cc] =
                __floats2half2_rn(s[nt][0], s[nt][1]);
            *(__half2*)&Ps[(rw + 8) * ROWH + cc] =
                __floats2half2_rn(s[nt][2], s[nt][3]);
        }
        __syncwarp();

        // O += P V  (16 x 64 per warp), 4 k-steps of 16; b from VTs[d][key]
#pragma unroll
        for (int kc = 0; kc < 4; kc++) {
            const int kb = kc * 16;
            unsigned pa[4];
            ldsm_x4(pa[0], pa[1], pa[2], pa[3], ps_base + a_loff + kb * 2);
#pragma unroll
            for (int ntp = 0; ntp < 4; ntp++) {
                unsigned bb[2], bb2[2];
                ldsm_x4(bb[0], bb[1], bb2[0], bb2[1],
                        vs_base + b_loff + (ntp * 16 * ROWH + kb) * 2);
                mma_f16(o[2 * ntp],     pa, bb);
                mma_f16(o[2 * ntp + 1], pa, bb2);
            }
        }
    }

    // epilogue -> fp16 ctx
    const float inv0 = 1.f / l0;
    const float inv1 = 1.f / l1;
    const size_t r0 = (size_t)(b * TT + q0 + rw) * CDIM + h * DD;
    const size_t r1 = (size_t)(b * TT + q0 + rw + 8) * CDIM + h * DD;
#pragma unroll
    for (int nt = 0; nt < 8; nt++) {
        const int cc = nt * 8 + 2 * tig;
        *(__half2*)&ctx[r0 + cc] =
            __floats2half2_rn(o[nt][0] * inv0, o[nt][1] * inv0);
        *(__half2*)&ctx[r1 + cc] =
            __floats2half2_rn(o[nt][2] * inv1, o[nt][3] * inv1);
    }
}

// ---------------------------------------------------------------------------
extern "C" void kernel_launch(void* const* d_in, const int* in_sizes, int n_in,
                              void* d_out, int out_size) {
    const float* x  = (const float*)d_in[0];
    const float* wq = (const float*)d_in[1];
    const float* wk = (const float*)d_in[2];
    const float* wv = (const float*)d_in[3];
    const float* wo = (const float*)d_in[4];
    float* out = (float*)d_out;

    __half *xh, *wqh, *wkh, *wvh, *woh, *qh, *kh, *vt, *ctxh;
    cudaGetSymbolAddress((void**)&xh,   g_xh);
    cudaGetSymbolAddress((void**)&wqh,  g_wqh);
    cudaGetSymbolAddress((void**)&wkh,  g_wkh);
    cudaGetSymbolAddress((void**)&wvh,  g_wvh);
    cudaGetSymbolAddress((void**)&woh,  g_woh);
    cudaGetSymbolAddress((void**)&qh,   g_qh);
    cudaGetSymbolAddress((void**)&kh,   g_kh);
    cudaGetSymbolAddress((void**)&vt,   g_vt);
    cudaGetSymbolAddress((void**)&ctxh, g_ctxh);

    cudaFuncSetAttribute(attn_mma_kernel,
                         cudaFuncAttributeMaxDynamicSharedMemorySize, ATTN_SMEM);

    // one-shot conversions (x + 4 weights) in a single launch
    const int NX = BT * CDIM / 4;
    const int NW = CDIM * CDIM / 4;
    convert_all_kernel<<<(NX + 4 * NW + 255) / 256, 256>>>(
        x, wq, wk, wv, wo, xh, wqh, wkh, wvh, woh);

    // fused QKV projections (fp16, V transposed per head)
    dim3 gq(CDIM / 128, BT / 128, 3);
    gemm_qkv_kernel<<<gq, 256>>>(xh, wqh, wkh, wvh, qh, kh, vt);

    dim3 ga(TT / 64, HH, BB);
    attn_mma_kernel<<<ga, 128, ATTN_SMEM>>>(qh, kh, vt, ctxh);

    dim3 gg(CDIM / 128, BT / 128);
    gemm_wo_kernel<<<gg, 256>>>(ctxh, woh, out);
}

// round 11
// speedup vs baseline: 3.2967x; 1.0633x over previous
#include <cuda_runtime.h>
#include <cuda_fp16.h>
#include <cstdint>

#define BB 2
#define TT 4096
#define CDIM 768
#define HH 12
#define DD 64
#define BT (BB*TT)   // 8192

// Scratch (allocation-free rule: __device__ globals)
__device__ __half g_xh[BT*CDIM];          // x in fp16
__device__ __half g_wqh[CDIM*CDIM];
__device__ __half g_wkh[CDIM*CDIM];
__device__ __half g_wvh[CDIM*CDIM];
__device__ __half g_woh[CDIM*CDIM];
__device__ __half g_qh[BT*CDIM];          // Q (pre-scaled incl. log2e) fp16
__device__ __half g_kh[BT*CDIM];          // K fp16 [BT][C]
__device__ __half g_vt[BB*CDIM*TT];       // V fp16 transposed: [(b*C + h*64+d)][t]
__device__ __half g_ctxh[BT*CDIM];        // attention output fp16

// ---------------------------------------------------------------------------
// helpers
// ---------------------------------------------------------------------------
__device__ __forceinline__ void mma_f16(float c[4], const unsigned a[4],
                                        const unsigned b[2]) {
    asm volatile(
        "mma.sync.aligned.m16n8k16.row.col.f32.f16.f16.f32 "
        "{%0,%1,%2,%3}, {%4,%5,%6,%7}, {%8,%9}, {%0,%1,%2,%3};\n"
        : "+f"(c[0]), "+f"(c[1]), "+f"(c[2]), "+f"(c[3])
        : "r"(a[0]), "r"(a[1]), "r"(a[2]), "r"(a[3]),
          "r"(b[0]), "r"(b[1]));
}

__device__ __forceinline__ void ldsm_x4(unsigned& r0, unsigned& r1,
                                        unsigned& r2, unsigned& r3,
                                        uint32_t addr) {
    asm volatile("ldmatrix.sync.aligned.m8n8.x4.shared.b16 {%0,%1,%2,%3}, [%4];"
                 : "=r"(r0), "=r"(r1), "=r"(r2), "=r"(r3) : "r"(addr));
}

__device__ __forceinline__ void cp_async16(uint32_t saddr, const void* gptr) {
    asm volatile("cp.async.cg.shared.global [%0], [%1], 16;"
                 :: "r"(saddr), "l"(gptr));
}
__device__ __forceinline__ void cp_async_commit() {
    asm volatile("cp.async.commit_group;");
}
__device__ __forceinline__ void cp_async_wait0() {
    asm volatile("cp.async.wait_group 0;");
}

__device__ __forceinline__ float fexp2(float x) {
    float y;
    asm("ex2.approx.f32 %0, %1;" : "=f"(y) : "f"(x));
    return y;
}

__device__ __forceinline__ unsigned packh2(float a, float b) {
    __half2 h = __floats2half2_rn(a, b);
    return *(unsigned*)&h;
}

// ---------------------------------------------------------------------------
// One-shot f32 -> f16 conversion of x + 4 weight matrices (single launch)
// ---------------------------------------------------------------------------
__global__ __launch_bounds__(256) void convert_all_kernel(
    const float* __restrict__ x,  const float* __restrict__ wq,
    const float* __restrict__ wk, const float* __restrict__ wv,
    const float* __restrict__ wo,
    __half* __restrict__ xh,  __half* __restrict__ wqh,
    __half* __restrict__ wkh, __half* __restrict__ wvh,
    __half* __restrict__ woh) {
    const int NX = BT * CDIM / 4;
    const int NW = CDIM * CDIM / 4;
    int i = blockIdx.x * blockDim.x + threadIdx.x;
    const float* src; __half* dst; int j;
    if (i < NX) {
        src = x; dst = xh; j = i;
    } else {
        int t = i - NX;
        int seg = t / NW;
        if (seg > 3) return;
        j = t - seg * NW;
        src = (seg == 0) ? wq : (seg == 1) ? wk : (seg == 2) ? wv : wo;
        dst = (seg == 0) ? wqh : (seg == 1) ? wkh : (seg == 2) ? wvh : woh;
    }
    float4 f = ((const float4*)src)[j];
    ((__half2*)dst)[2 * j]     = __floats2half2_rn(f.x, f.y);
    ((__half2*)dst)[2 * j + 1] = __floats2half2_rn(f.z, f.w);
}

// ---------------------------------------------------------------------------
// fp16 GEMM core: one MROWS x 128 tile of Y = X * W^T.
// BK=32, cp.async double-buffered, 8 warps (2M x 4N).
// MROWS=128: warp tile 64x32. MROWS=64: warp tile 32x32.
// OUT_MODE: 0 = fp16 [BT][C] scaled, 1 = fp16 V-transposed, 2 = f32 [BT][C].
// ---------------------------------------------------------------------------
template <int MROWS>
__device__ __forceinline__ void gemm_tile_f16(
    const __half* __restrict__ X, const __half* __restrict__ W,
    void* __restrict__ Yv, float out_scale, int out_mode,
    int m0, int n0, __half* As, __half* Bs) {

    constexpr int MT = MROWS / 32;         // mt count per wm half
    constexpr int ASTG = MROWS * 40;       // A stage stride (halves)
    constexpr int BSTG = 128 * 40;

    const int tid  = threadIdx.x;
    const int warp = tid >> 5;
    const int lane = tid & 31;
    const int gid  = lane >> 2;   // 0..7
    const int tig  = lane & 3;    // 0..3
    const int wm   = warp >> 2;   // 0..1
    const int wn   = warp & 3;    // 0..3

    const int lrow = tid >> 2;         // 0..63
    const int lch  = (tid & 3) * 8;    // half offset 0,8,16,24

    const uint32_t a_smb = (uint32_t)__cvta_generic_to_shared(As);
    const uint32_t b_smb = (uint32_t)__cvta_generic_to_shared(Bs);

    // ldmatrix lane offsets (bytes), row stride 40 halves
    const uint32_t a_loff =
        (((wm * (MT * 16) + (lane & 15)) * 40) + (lane >> 4) * 8) * 2;
    const uint32_t b_loff =
        ((((lane >> 4) * 8 + (lane & 7)) * 40) + ((lane >> 3) & 1) * 8) * 2;

    float c[MT][4][4];
#pragma unroll
    for (int mt = 0; mt < MT; mt++)
#pragma unroll
        for (int nt = 0; nt < 4; nt++)
#pragma unroll
            for (int i = 0; i < 4; i++) c[mt][nt][i] = 0.f;

    // prologue: stage 0 <- k0 = 0
#pragma unroll
    for (int i = 0; i < MROWS / 64; i++) {
        const int r = lrow + i * 64;
        cp_async16(a_smb + (r * 40 + lch) * 2, &X[(size_t)(m0 + r) * CDIM + lch]);
    }
#pragma unroll
    for (int i = 0; i < 2; i++) {
        const int r = lrow + i * 64;
        cp_async16(b_smb + (r * 40 + lch) * 2, &W[(size_t)(n0 + r) * CDIM + lch]);
    }
    cp_async_commit();

    for (int k0 = 0; k0 < CDIM; k0 += 32) {
        const int s = (k0 >> 5) & 1;
        cp_async_wait0();
        __syncthreads();

        if (k0 + 32 < CDIM) {
            const int ns = s ^ 1;
#pragma unroll
            for (int i = 0; i < MROWS / 64; i++) {
                const int r = lrow + i * 64;
                cp_async16(a_smb + (ns * ASTG + r * 40 + lch) * 2,
                           &X[(size_t)(m0 + r) * CDIM + k0 + 32 + lch]);
            }
#pragma unroll
            for (int i = 0; i < 2; i++) {
                const int r = lrow + i * 64;
                cp_async16(b_smb + (ns * BSTG + r * 40 + lch) * 2,
                           &W[(size_t)(n0 + r) * CDIM + k0 + 32 + lch]);
            }
            cp_async_commit();
        }

#pragma unroll
        for (int ks = 0; ks < 2; ks++) {
            const int kb = ks * 16;
            unsigned a[MT][4], b[4][2];
#pragma unroll
            for (int mt = 0; mt < MT; mt++)
                ldsm_x4(a[mt][0], a[mt][1], a[mt][2], a[mt][3],
                        a_smb + (s * ASTG) * 2 + a_loff + (mt * 16 * 40 + kb) * 2);
#pragma unroll
            for (int ntp = 0; ntp < 2; ntp++)
                ldsm_x4(b[2 * ntp][0], b[2 * ntp][1],
                        b[2 * ntp + 1][0], b[2 * ntp + 1][1],
                        b_smb + (s * BSTG) * 2 + b_loff +
                            ((wn * 32 + ntp * 16) * 40 + kb) * 2);
#pragma unroll
            for (int mt = 0; mt < MT; mt++)
#pragma unroll
                for (int nt = 0; nt < 4; nt++)
                    mma_f16(c[mt][nt], a[mt], b[nt]);
        }
    }

    // epilogue
#pragma unroll
    for (int mt = 0; mt < MT; mt++) {
        const int gr = m0 + wm * (MT * 16) + mt * 16 + gid;   // global row (token)
#pragma unroll
        for (int nt = 0; nt < 4; nt++) {
            const int cn = n0 + wn * 32 + nt * 8 + 2 * tig;
            if (out_mode == 0) {
                __half* Y = (__half*)Yv;
                *(__half2*)&Y[(size_t)gr * CDIM + cn] =
                    __floats2half2_rn(c[mt][nt][0] * out_scale,
                                      c[mt][nt][1] * out_scale);
                *(__half2*)&Y[(size_t)(gr + 8) * CDIM + cn] =
                    __floats2half2_rn(c[mt][nt][2] * out_scale,
                                      c[mt][nt][3] * out_scale);
            } else if (out_mode == 1) {
                __half* Y = (__half*)Yv;
                const int bi = gr >> 12;
                const int t  = gr & (TT - 1);
                const size_t base = (size_t)bi * CDIM * TT;
                Y[base + (size_t)cn * TT + t]           = __float2half(c[mt][nt][0]);
                Y[base + (size_t)(cn + 1) * TT + t]     = __float2half(c[mt][nt][1]);
                Y[base + (size_t)cn * TT + t + 8]       = __float2half(c[mt][nt][2]);
                Y[base + (size_t)(cn + 1) * TT + t + 8] = __float2half(c[mt][nt][3]);
            } else {
                float* Y = (float*)Yv;
                *(float2*)&Y[(size_t)gr * CDIM + cn] =
                    make_float2(c[mt][nt][0], c[mt][nt][1]);
                *(float2*)&Y[(size_t)(gr + 8) * CDIM + cn] =
                    make_float2(c[mt][nt][2], c[mt][nt][3]);
            }
        }
    }
}

// Fused QKV: gridDim.z = 3 selects {wq->qh(x scale), wk->kh, wv->vt}.
// Q pre-scale includes log2(e) so attention can use raw ex2.
__global__ __launch_bounds__(256) void gemm_qkv_kernel(
    const __half* __restrict__ X,
    const __half* __restrict__ wq, const __half* __restrict__ wk,
    const __half* __restrict__ wv,
    __half* __restrict__ q, __half* __restrict__ k, __half* __restrict__ vt) {
    __shared__ __half As[2][128][40];
    __shared__ __half Bs[2][128][40];

    const int z = blockIdx.z;
    const __half* W = (z == 0) ? wq : (z == 1) ? wk : wv;
    void*         Y = (z == 0) ? (void*)q : (z == 1) ? (void*)k : (void*)vt;
    const float scale = (z == 0) ? 0.125f * 1.44269504088896341f : 1.0f;
    const int mode = (z == 2) ? 1 : 0;

    gemm_tile_f16<128>(X, W, Y, scale, mode, blockIdx.y * 128, blockIdx.x * 128,
                       &As[0][0][0], &Bs[0][0][0]);
}

// Output projection: ctxh * wo^T -> f32 out. 64-row tiles (768 blocks) for
// better wave quantization (2.6 waves vs 1.3).
__global__ __launch_bounds__(256) void gemm_wo_kernel(
    const __half* __restrict__ X, const __half* __restrict__ W,
    float* __restrict__ Y) {
    __shared__ __half As[2][64][40];
    __shared__ __half Bs[2][128][40];
    gemm_tile_f16<64>(X, W, Y, 1.0f, 2, blockIdx.y * 64, blockIdx.x * 128,
                      &As[0][0][0], &Bs[0][0][0]);
}

// ---------------------------------------------------------------------------
// Flash attention (causal), fp16 mma k16, online softmax (base-2 domain).
// Proven loop structure (serial K/V cp.async per tile, wait0, 2 syncs/iter,
// qt reversed). P built DIRECTLY from S C-fragments (no smem round-trip).
// ---------------------------------------------------------------------------
#define ROWH 72
#define ATTN_SMEM (3 * 64 * ROWH * 2)

__global__ __launch_bounds__(128) void attn_mma_kernel(
    const __half* __restrict__ q, const __half* __restrict__ k,
    const __half* __restrict__ vt, __half* __restrict__ ctx) {
    extern __shared__ __half smh[];
    __half* Qs  = smh;
    __half* Ks  = smh + 64 * ROWH;
    __half* VTs = smh + 2 * 64 * ROWH;   // [d][key]

    const int tid  = threadIdx.x;
    const int warp = tid >> 5;
    const int lane = tid & 31;
    const int gid  = lane >> 2;
    const int tig  = lane & 3;
    const int rw   = warp * 16 + gid;    // this thread's first local row

    const int qt = gridDim.x - 1 - blockIdx.x;   // long blocks first
    const int h  = blockIdx.y;
    const int b  = blockIdx.z;
    const int q0 = qt * 64;

    const uint32_t qs_base = (uint32_t)__cvta_generic_to_shared(Qs);
    const uint32_t ks_base = (uint32_t)__cvta_generic_to_shared(Ks);
    const uint32_t vs_base = (uint32_t)__cvta_generic_to_shared(VTs);

    // ldmatrix lane offsets (bytes), row stride ROWH halves
    const uint32_t b_loff =
        ((((lane >> 4) * 8 + (lane & 7)) * ROWH) + ((lane >> 3) & 1) * 8) * 2;
    const uint32_t a_loff =
        (((warp * 16 + (lane & 15)) * ROWH) + (lane >> 4) * 8) * 2;

    // Q tile (fp16, pre-scaled incl. log2e): 64 rows x 128B
    for (int e = tid; e < 512; e += 128) {
        int rr = e >> 3, c8 = (e & 7) * 8;
        cp_async16(qs_base + (rr * ROWH + c8) * 2,
                   &q[(size_t)(b * TT + q0 + rr) * CDIM + h * DD + c8]);
    }
    cp_async_commit();
    cp_async_wait0();
    __syncthreads();

    // Q fragments (k16 x 4 steps) via ldmatrix
    unsigned qa[4][4];
#pragma unroll
    for (int ks = 0; ks < 4; ks++)
        ldsm_x4(qa[ks][0], qa[ks][1], qa[ks][2], qa[ks][3],
                qs_base + a_loff + (ks * 16) * 2);

    float o[8][4];
#pragma unroll
    for (int nt = 0; nt < 8; nt++)
#pragma unroll
        for (int i = 0; i < 4; i++) o[nt][i] = 0.f;
    float m0r = -1e30f, m1r = -1e30f, l0 = 0.f, l1 = 0.f;

    for (int jt = 0; jt <= qt; jt++) {
        __syncthreads();   // prior compute done before smem overwrite
        for (int e = tid; e < 512; e += 128) {
            int rr = e >> 3, c8 = (e & 7) * 8;
            cp_async16(ks_base + (rr * ROWH + c8) * 2,
                       &k[(size_t)(b * TT + jt * 64 + rr) * CDIM + h * DD + c8]);
            cp_async16(vs_base + (rr * ROWH + c8) * 2,
                       &vt[(size_t)(b * CDIM + h * DD + rr) * TT + jt * 64 + c8]);
        }
        cp_async_commit();
        cp_async_wait0();
        __syncthreads();

        // S = Q K^T  (16 x 64 per warp), 4 k-steps of 16 (base-2 logits)
        float s[8][4];
#pragma unroll
        for (int nt = 0; nt < 8; nt++)
#pragma unroll
            for (int i = 0; i < 4; i++) s[nt][i] = 0.f;

#pragma unroll
        for (int ks = 0; ks < 4; ks++) {
            const int kb = ks * 16;
#pragma unroll
            for (int ntp = 0; ntp < 4; ntp++) {
                unsigned bb[2], bb2[2];
                ldsm_x4(bb[0], bb[1], bb2[0], bb2[1],
                        ks_base + b_loff + (ntp * 16 * ROWH + kb) * 2);
                mma_f16(s[2 * ntp],     qa[ks], bb);
                mma_f16(s[2 * ntp + 1], qa[ks], bb2);
            }
        }

        // causal mask (diagonal tile only)
        if (jt == qt) {
#pragma unroll
            for (int nt = 0; nt < 8; nt++) {
                const int cg = nt * 8 + 2 * tig;
                if (cg > rw)         s[nt][0] = -1e30f;
                if (cg + 1 > rw)     s[nt][1] = -1e30f;
                if (cg > rw + 8)     s[nt][2] = -1e30f;
                if (cg + 1 > rw + 8) s[nt][3] = -1e30f;
            }
        }

        // row maxima (two rows per thread)
        float mx0 = -1e30f, mx1 = -1e30f;
#pragma unroll
        for (int nt = 0; nt < 8; nt++) {
            mx0 = fmaxf(mx0, fmaxf(s[nt][0], s[nt][1]));
            mx1 = fmaxf(mx1, fmaxf(s[nt][2], s[nt][3]));
        }
        mx0 = fmaxf(mx0, __shfl_xor_sync(0xffffffffu, mx0, 1));
        mx0 = fmaxf(mx0, __shfl_xor_sync(0xffffffffu, mx0, 2));
        mx1 = fmaxf(mx1, __shfl_xor_sync(0xffffffffu, mx1, 1));
        mx1 = fmaxf(mx1, __shfl_xor_sync(0xffffffffu, mx1, 2));

        const float mn0 = fmaxf(m0r, mx0);
        const float mn1 = fmaxf(m1r, mx1);
        const float a0 = fexp2(m0r - mn0);
        const float a1 = fexp2(m1r - mn1);

        float ls0 = 0.f, ls1 = 0.f;
#pragma unroll
        for (int nt = 0; nt < 8; nt++) {
            s[nt][0] = fexp2(s[nt][0] - mn0); ls0 += s[nt][0];
            s[nt][1] = fexp2(s[nt][1] - mn0); ls0 += s[nt][1];
            s[nt][2] = fexp2(s[nt][2] - mn1); ls1 += s[nt][2];
            s[nt][3] = fexp2(s[nt][3] - mn1); ls1 += s[nt][3];
        }
        ls0 += __shfl_xor_sync(0xffffffffu, ls0, 1);
        ls0 += __shfl_xor_sync(0xffffffffu, ls0, 2);
        ls1 += __shfl_xor_sync(0xffffffffu, ls1, 1);
        ls1 += __shfl_xor_sync(0xffffffffu, ls1, 2);

        l0 = l0 * a0 + ls0; m0r = mn0;
        l1 = l1 * a1 + ls1; m1r = mn1;
#pragma unroll
        for (int nt = 0; nt < 8; nt++) {
            o[nt][0] *= a0; o[nt][1] *= a0;
            o[nt][2] *= a1; o[nt][3] *= a1;
        }

        // O += P V : P built DIRECTLY from S C-fragments (no smem round-trip).
        // a-frag for k-block kc*16: rows gid/gid+8, k cols 2tig(+1), +8
        //   pa0=(gid, kc16+2tig,+1)   = s[2kc][0..1]
        //   pa1=(gid+8, same)         = s[2kc][2..3]
        //   pa2=(gid, kc16+8+2tig,+1) = s[2kc+1][0..1]
        //   pa3=(gid+8, same)         = s[2kc+1][2..3]
#pragma unroll
        for (int kc = 0; kc < 4; kc++) {
            unsigned pa[4];
            pa[0] = packh2(s[2 * kc][0],     s[2 * kc][1]);
            pa[1] = packh2(s[2 * kc][2],     s[2 * kc][3]);
            pa[2] = packh2(s[2 * kc + 1][0], s[2 * kc + 1][1]);
            pa[3] = packh2(s[2 * kc + 1][2], s[2 * kc + 1][3]);
            const int kb = kc * 16;
#pragma unroll
            for (int ntp = 0; ntp < 4; ntp++) {
                unsigned bb[2], bb2[2];
                ldsm_x4(bb[0], bb[1], bb2[0], bb2[1],
                        vs_base + b_loff + (ntp * 16 * ROWH + kb) * 2);
                mma_f16(o[2 * ntp],     pa, bb);
                mma_f16(o[2 * ntp + 1], pa, bb2);
            }
        }
    }

    // epilogue -> fp16 ctx
    const float inv0 = 1.f / l0;
    const float inv1 = 1.f / l1;
    const size_t r0 = (size_t)(b * TT + q0 + rw) * CDIM + h * DD;
    const size_t r1 = (size_t)(b * TT + q0 + rw + 8) * CDIM + h * DD;
#pragma unroll
    for (int nt = 0; nt < 8; nt++) {
        const int cc = nt * 8 + 2 * tig;
        *(__half2*)&ctx[r0 + cc] =
            __floats2half2_rn(o[nt][0] * inv0, o[nt][1] * inv0);
        *(__half2*)&ctx[r1 + cc] =
            __floats2half2_rn(o[nt][2] * inv1, o[nt][3] * inv1);
    }
}

// ---------------------------------------------------------------------------
extern "C" void kernel_launch(void* const* d_in, const int* in_sizes, int n_in,
                              void* d_out, int out_size) {
    const float* x  = (const float*)d_in[0];
    const float* wq = (const float*)d_in[1];
    const float* wk = (const float*)d_in[2];
    const float* wv = (const float*)d_in[3];
    const float* wo = (const float*)d_in[4];
    float* out = (float*)d_out;

    __half *xh, *wqh, *wkh, *wvh, *woh, *qh, *kh, *vt, *ctxh;
    cudaGetSymbolAddress((void**)&xh,   g_xh);
    cudaGetSymbolAddress((void**)&wqh,  g_wqh);
    cudaGetSymbolAddress((void**)&wkh,  g_wkh);
    cudaGetSymbolAddress((void**)&wvh,  g_wvh);
    cudaGetSymbolAddress((void**)&woh,  g_woh);
    cudaGetSymbolAddress((void**)&qh,   g_qh);
    cudaGetSymbolAddress((void**)&kh,   g_kh);
    cudaGetSymbolAddress((void**)&vt,   g_vt);
    cudaGetSymbolAddress((void**)&ctxh, g_ctxh);

    cudaFuncSetAttribute(attn_mma_kernel,
                         cudaFuncAttributeMaxDynamicSharedMemorySize, ATTN_SMEM);

    // one-shot conversions (x + 4 weights) in a single launch
    const int NX = BT * CDIM / 4;
    const int NW = CDIM * CDIM / 4;
    convert_all_kernel<<<(NX + 4 * NW + 255) / 256, 256>>>(
        x, wq, wk, wv, wo, xh, wqh, wkh, wvh, woh);

    // fused QKV projections (fp16, V transposed per head, Q scaled by
    // 0.125*log2e for base-2 softmax)
    dim3 gq(CDIM / 128, BT / 128, 3);
    gemm_qkv_kernel<<<gq, 256>>>(xh, wqh, wkh, wvh, qh, kh, vt);

    dim3 ga(TT / 64, HH, BB);
    attn_mma_kernel<<<ga, 128, ATTN_SMEM>>>(qh, kh, vt, ctxh);

    dim3 gg(CDIM / 128, BT / 64);
    gemm_wo_kernel<<<gg, 256>>>(ctxh, woh, out);
}